// round 1
// baseline (speedup 1.0000x reference)
#include <cuda_runtime.h>
#include <math.h>

typedef unsigned long long u64;

// ---------------- scratch (no allocations allowed) ----------------
__device__ float g_q[64 * 1024 * 128];      // [B*H, S, 128]
__device__ float g_attn_out[2048 * 4096];   // [B*S, H*128]

// ---------------- SGEMM: C = A[2048,K] @ B[K,N] + bias ----------------
// MODE 0: plain row-major out0[r*N+c]
// MODE 1: QKV routing: cols [0,4096)->g_q [B,H,S,128]; [4096,8192)->outK cache; [8192,12288)->outV cache
#define BM 128
#define BN 128
#define BK 16

template<int MODE>
__global__ void __launch_bounds__(256, 2) sgemm_kernel(
    const float* __restrict__ A, const float* __restrict__ B,
    const float* __restrict__ bias, int N, int K,
    float* __restrict__ out0, float* __restrict__ outK, float* __restrict__ outV)
{
    __shared__ float As[2][BK][BM];
    __shared__ float Bs[2][BK][BN];
    const int tid = threadIdx.x;
    const int bm = blockIdx.y * BM;
    const int bn = blockIdx.x * BN;

    const int a_row = tid >> 2;          // 0..63
    const int a_col = (tid & 3) << 2;    // 0,4,8,12
    const int b_row = tid >> 5;          // 0..7
    const int b_col = (tid & 31) << 2;   // 0..124

    const int tr = (tid >> 4) << 2;      // 0..60 step 4
    const int tc = (tid & 15) << 2;      // 0..60 step 4

    const float* Aptr = A + (size_t)(bm + a_row) * K + a_col;
    const float* Bptr = B + (size_t)b_row * N + bn + b_col;

    // prologue: tile 0
    {
        float4 a0 = *(const float4*)(Aptr);
        float4 a1 = *(const float4*)(Aptr + (size_t)64 * K);
        float4 b0 = *(const float4*)(Bptr);
        float4 b1 = *(const float4*)(Bptr + (size_t)8 * N);
        As[0][a_col+0][a_row] = a0.x; As[0][a_col+1][a_row] = a0.y;
        As[0][a_col+2][a_row] = a0.z; As[0][a_col+3][a_row] = a0.w;
        As[0][a_col+0][a_row+64] = a1.x; As[0][a_col+1][a_row+64] = a1.y;
        As[0][a_col+2][a_row+64] = a1.z; As[0][a_col+3][a_row+64] = a1.w;
        *(float4*)&Bs[0][b_row][b_col] = b0;
        *(float4*)&Bs[0][b_row+8][b_col] = b1;
    }
    __syncthreads();

    u64 acc2[8][4];
    #pragma unroll
    for (int i = 0; i < 8; i++)
        #pragma unroll
        for (int j = 0; j < 4; j++) acc2[i][j] = 0ull;

    int buf = 0;
    for (int kt = 0; kt < K; kt += BK) {
        const bool has_next = (kt + BK) < K;
        float4 a0n, a1n, b0n, b1n;
        if (has_next) {
            a0n = *(const float4*)(Aptr + kt + BK);
            a1n = *(const float4*)(Aptr + kt + BK + (size_t)64 * K);
            b0n = *(const float4*)(Bptr + (size_t)(kt + BK) * N);
            b1n = *(const float4*)(Bptr + (size_t)(kt + BK + 8) * N);
        }
        #pragma unroll
        for (int k = 0; k < BK; k++) {
            float a[8];
            *(float4*)&a[0] = *(const float4*)&As[buf][k][tr];
            *(float4*)&a[4] = *(const float4*)&As[buf][k][tr + 64];
            u64 b2[4];
            {
                ulonglong2 t0 = *(const ulonglong2*)&Bs[buf][k][tc];
                ulonglong2 t1 = *(const ulonglong2*)&Bs[buf][k][tc + 64];
                b2[0] = t0.x; b2[1] = t0.y; b2[2] = t1.x; b2[3] = t1.y;
            }
            #pragma unroll
            for (int i = 0; i < 8; i++) {
                u64 a2;
                asm("mov.b64 %0, {%1, %1};" : "=l"(a2) : "f"(a[i]));
                #pragma unroll
                for (int j = 0; j < 4; j++)
                    asm("fma.rn.f32x2 %0, %1, %2, %0;" : "+l"(acc2[i][j]) : "l"(a2), "l"(b2[j]));
            }
        }
        if (has_next) {
            const int nb = buf ^ 1;
            As[nb][a_col+0][a_row] = a0n.x; As[nb][a_col+1][a_row] = a0n.y;
            As[nb][a_col+2][a_row] = a0n.z; As[nb][a_col+3][a_row] = a0n.w;
            As[nb][a_col+0][a_row+64] = a1n.x; As[nb][a_col+1][a_row+64] = a1n.y;
            As[nb][a_col+2][a_row+64] = a1n.z; As[nb][a_col+3][a_row+64] = a1n.w;
            *(float4*)&Bs[nb][b_row][b_col] = b0n;
            *(float4*)&Bs[nb][b_row+8][b_col] = b1n;
            __syncthreads();
            buf = nb;
        }
    }

    // epilogue
    #pragma unroll
    for (int i = 0; i < 8; i++) {
        const int lr = (i < 4) ? (tr + i) : (64 + tr + i - 4);
        const int r = bm + lr;
        #pragma unroll
        for (int jp = 0; jp < 4; jp++) {
            float lo, hi;
            asm("mov.b64 {%0, %1}, %2;" : "=f"(lo), "=f"(hi) : "l"(acc2[i][jp]));
            const int c0 = bn + ((jp < 2) ? (tc + jp*2) : (64 + tc + (jp-2)*2));
            #pragma unroll
            for (int e = 0; e < 2; e++) {
                const int c = c0 + e;
                const float v = ((e == 0) ? lo : hi) + bias[c];
                if (MODE == 0) {
                    out0[(size_t)r * N + c] = v;
                } else {
                    const int b = r >> 10, s = r & 1023;
                    const int seg = c >> 12, w = c & 4095;
                    const int h = w >> 7, dd = w & 127;
                    if (seg == 0)
                        g_q[(((size_t)(b*32 + h)) * 1024 + s) * 128 + dd] = v;
                    else if (seg == 1)
                        outK[(((size_t)(b*32 + h)) * 2048 + s) * 128 + dd] = v;
                    else
                        outV[(((size_t)(b*32 + h)) * 2048 + s) * 128 + dd] = v;
                }
            }
        }
    }
}

// ---------------- Flash attention (causal, fp32) ----------------
// grid: (16 q-tiles, 64 bh). 256 threads: thread = (row = tid>>2, quad lane cq = tid&3)
#define QP 132   // padded row pitch for 128-wide tiles
#define PP 68    // padded row pitch for 64-wide score tile

__global__ void __launch_bounds__(256) attn_kernel(
    const float* __restrict__ Kc, const float* __restrict__ Vc)
{
    extern __shared__ float smf[];
    float* sQ = smf;
    float* sK = smf + 64 * QP;
    float* sV = smf + 2 * 64 * QP;
    float* sP = smf + 3 * 64 * QP;

    const int qt = blockIdx.x;
    const int bh = blockIdx.y;
    const int b = bh >> 5;
    const int h = bh & 31;
    const int tid = threadIdx.x;
    const int row = tid >> 2;
    const int cq = tid & 3;

    // load Q tile [64,128]
    const float* Qb = g_q + ((size_t)bh * 1024 + (size_t)qt * 64) * 128;
    #pragma unroll
    for (int it = 0; it < 8; it++) {
        const int f4 = tid + it * 256;
        const int rr = f4 >> 5, c4 = (f4 & 31) << 2;
        *(float4*)&sQ[rr * QP + c4] = *(const float4*)(Qb + rr * 128 + c4);
    }

    float o[32];
    #pragma unroll
    for (int i = 0; i < 32; i++) o[i] = 0.f;
    float mrow = -INFINITY, lrow = 0.f;
    const float scale = 0.08838834764831845f;
    const int qglob = qt * 64 + row;

    const float* Kb0 = Kc + (size_t)bh * 2048 * 128;
    const float* Vb0 = Vc + (size_t)bh * 2048 * 128;

    for (int kt = 0; kt <= qt; kt++) {
        __syncthreads();  // protect sK/sV from previous iteration's readers
        const float* Kb = Kb0 + (size_t)kt * 64 * 128;
        const float* Vb = Vb0 + (size_t)kt * 64 * 128;
        #pragma unroll
        for (int it = 0; it < 8; it++) {
            const int f4 = tid + it * 256;
            const int rr = f4 >> 5, c4 = (f4 & 31) << 2;
            *(float4*)&sK[rr * QP + c4] = *(const float4*)(Kb + rr * 128 + c4);
            *(float4*)&sV[rr * QP + c4] = *(const float4*)(Vb + rr * 128 + c4);
        }
        __syncthreads();

        // scores: this thread covers cols c = cq + 4*j, j=0..15 of the 64-key tile
        float p[16];
        #pragma unroll
        for (int j = 0; j < 16; j++) p[j] = 0.f;
        #pragma unroll 4
        for (int d = 0; d < 128; d += 4) {
            const float4 qv = *(const float4*)&sQ[row * QP + d];
            #pragma unroll
            for (int j = 0; j < 16; j++) {
                const float4 kv = *(const float4*)&sK[(cq + 4*j) * QP + d];
                p[j] += qv.x*kv.x + qv.y*kv.y + qv.z*kv.z + qv.w*kv.w;
            }
        }
        float tmax = -INFINITY;
        #pragma unroll
        for (int j = 0; j < 16; j++) {
            const int kg = kt * 64 + cq + 4*j;
            p[j] = (kg <= qglob) ? p[j] * scale : -INFINITY;
            tmax = fmaxf(tmax, p[j]);
        }
        tmax = fmaxf(tmax, __shfl_xor_sync(0xffffffffu, tmax, 1));
        tmax = fmaxf(tmax, __shfl_xor_sync(0xffffffffu, tmax, 2));
        const float mnew = fmaxf(mrow, tmax);
        const float corr = __expf(mrow - mnew);
        float tsum = 0.f;
        #pragma unroll
        for (int j = 0; j < 16; j++) {
            const float e = __expf(p[j] - mnew);
            p[j] = e; tsum += e;
        }
        tsum += __shfl_xor_sync(0xffffffffu, tsum, 1);
        tsum += __shfl_xor_sync(0xffffffffu, tsum, 2);
        lrow = lrow * corr + tsum;
        mrow = mnew;
        #pragma unroll
        for (int i = 0; i < 32; i++) o[i] *= corr;
        #pragma unroll
        for (int j = 0; j < 16; j++) sP[row * PP + cq + 4*j] = p[j];
        __syncthreads();

        // PV: thread owns d = cq*4 + 16*jj + {0..3}
        #pragma unroll 4
        for (int c = 0; c < 64; c++) {
            const float pv = sP[row * PP + c];
            #pragma unroll
            for (int jj = 0; jj < 8; jj++) {
                const float4 vv = *(const float4*)&sV[c * QP + cq*4 + jj*16];
                o[jj*4+0] += pv * vv.x;
                o[jj*4+1] += pv * vv.y;
                o[jj*4+2] += pv * vv.z;
                o[jj*4+3] += pv * vv.w;
            }
        }
    }

    const float inv = 1.f / lrow;
    float* Ob = g_attn_out + ((size_t)(b * 1024 + qglob)) * 4096 + h * 128;
    #pragma unroll
    for (int jj = 0; jj < 8; jj++) {
        float4 v4;
        v4.x = o[jj*4+0] * inv; v4.y = o[jj*4+1] * inv;
        v4.z = o[jj*4+2] * inv; v4.w = o[jj*4+3] * inv;
        *(float4*)(Ob + cq*4 + jj*16) = v4;
    }
}

// ---------------- launch ----------------
extern "C" void kernel_launch(void* const* d_in, const int* in_sizes, int n_in,
                              void* d_out, int out_size)
{
    const float* x       = (const float*)d_in[0];
    // d_in[1] = mask (analytically causal; unused)
    const float* W_qkv   = (const float*)d_in[2];
    const float* b_qkv   = (const float*)d_in[3];
    const float* W_out   = (const float*)d_in[4];
    const float* b_out   = (const float*)d_in[5];
    const float* cache_k = (const float*)d_in[6];
    const float* cache_v = (const float*)d_in[7];

    float* out  = (float*)d_out;
    float* y    = out;                       // [2,1024,4096]
    float* outK = out + 8388608;             // [2,32,2048,128]
    float* outV = out + 25165824;            // [2,32,2048,128]

    // preserve untouched cache slots (slots >= 1024), then overwrite first 1024
    cudaMemcpyAsync(outK, cache_k, (size_t)16777216 * sizeof(float),
                    cudaMemcpyDeviceToDevice, 0);
    cudaMemcpyAsync(outV, cache_v, (size_t)16777216 * sizeof(float),
                    cudaMemcpyDeviceToDevice, 0);

    dim3 blk(256);

    // QKV projection + bias + scatter (q -> g_q, k/v -> cache)
    sgemm_kernel<1><<<dim3(96, 16), blk>>>(x, W_qkv, b_qkv, 12288, 4096,
                                           nullptr, outK, outV);

    // causal flash attention
    const size_t att_smem = (size_t)(3 * 64 * QP + 64 * PP) * sizeof(float);
    cudaFuncSetAttribute(attn_kernel, cudaFuncAttributeMaxDynamicSharedMemorySize,
                         (int)att_smem);
    attn_kernel<<<dim3(16, 64), blk, att_smem>>>(outK, outV);

    // output projection
    float* attn_out_ptr = nullptr;
    cudaGetSymbolAddress((void**)&attn_out_ptr, g_attn_out);
    sgemm_kernel<0><<<dim3(32, 16), blk>>>(attn_out_ptr, W_out, b_out, 4096, 4096,
                                           y, nullptr, nullptr);
}

// round 3
// speedup vs baseline: 2.2526x; 2.2526x over previous
#include <cuda_runtime.h>
#include <cuda_fp16.h>
#include <math.h>
#include <cstdint>

typedef unsigned long long u64;

// ==================== scratch (no allocations allowed) ====================
__device__ __align__(128) float g_q[64 * 1024 * 128];        // [B*H, S, 128]
__device__ __align__(128) float g_attn_out[2048 * 4096];     // [B*S, H*128]
__device__ __align__(128) __half g_ahi[2048 * 4096];
__device__ __align__(128) __half g_alo[2048 * 4096];
__device__ __align__(128) __half g_bqkv[12288 * 4096];       // [N,K] fp16
__device__ __align__(128) __half g_wout[4096 * 4096];        // [N,K] fp16

// ==================== PTX helpers (baseline ISA only) ====================
__device__ __forceinline__ uint32_t smem_u32(const void* p) {
    uint32_t a;
    asm("{ .reg .u64 t; cvta.to.shared.u64 t, %1; cvt.u32.u64 %0, t; }" : "=r"(a) : "l"(p));
    return a;
}
__device__ __forceinline__ void cp16(uint32_t dst, const void* src) {
    asm volatile("cp.async.cg.shared.global [%0], [%1], 16;" :: "r"(dst), "l"(src));
}
__device__ __forceinline__ void cp_commit() { asm volatile("cp.async.commit_group;" ::: "memory"); }
template <int N> __device__ __forceinline__ void cp_wait() { asm volatile("cp.async.wait_group %0;" :: "n"(N) : "memory"); }

#define LDSM_X4(r0, r1, r2, r3, addr) \
    asm volatile("ldmatrix.sync.aligned.m8n8.x4.shared.b16 {%0,%1,%2,%3}, [%4];" \
        : "=r"(r0), "=r"(r1), "=r"(r2), "=r"(r3) : "r"(addr))

#define MMA16816(d, a0, a1, a2, a3, b0, b1) \
    asm volatile("mma.sync.aligned.m16n8k16.row.col.f32.f16.f16.f32 " \
        "{%0,%1,%2,%3},{%4,%5,%6,%7},{%8,%9},{%0,%1,%2,%3};" \
        : "+f"((d)[0]), "+f"((d)[1]), "+f"((d)[2]), "+f"((d)[3]) \
        : "r"(a0), "r"(a1), "r"(a2), "r"(a3), "r"(b0), "r"(b1))

// swizzle: 128B rows, 16B chunks; chunk ^= (row & 7)
#define SMEM_SWZ(off) ((off) ^ (((off) >> 3) & 0x70))

// ==================== split kernels ====================
// A (fp32, O(1) values) -> hi fp16 + lo fp16 (residual)
__global__ void __launch_bounds__(256) split_a_kernel(const float* __restrict__ in,
                                                      __half* __restrict__ hi, __half* __restrict__ lo) {
    const size_t i = (size_t)blockIdx.x * 256 + threadIdx.x;
    float4 v = ((const float4*)in)[i];
    __half h0 = __float2half_rn(v.x), h1 = __float2half_rn(v.y);
    __half h2 = __float2half_rn(v.z), h3 = __float2half_rn(v.w);
    __half l0 = __float2half_rn(v.x - __half2float(h0));
    __half l1 = __float2half_rn(v.y - __half2float(h1));
    __half l2 = __float2half_rn(v.z - __half2float(h2));
    __half l3 = __float2half_rn(v.w - __half2float(h3));
    __half2* hp = (__half2*)hi;
    __half2* lp = (__half2*)lo;
    hp[2 * i] = __half2{h0, h1}; hp[2 * i + 1] = __half2{h2, h3};
    lp[2 * i] = __half2{l0, l1}; lp[2 * i + 1] = __half2{l2, l3};
}

// W: [K,N] fp32 row-major -> [N,K] fp16 row-major (single precision level)
__global__ void __launch_bounds__(256) splitT_kernel(const float* __restrict__ in,
                                                     __half* __restrict__ outT, int K, int N) {
    __shared__ float t[32][33];
    const int n0 = blockIdx.x * 32, k0 = blockIdx.y * 32;
    for (int i = threadIdx.y; i < 32; i += 8)
        t[i][threadIdx.x] = in[(size_t)(k0 + i) * N + n0 + threadIdx.x];
    __syncthreads();
    for (int i = threadIdx.y; i < 32; i += 8) {
        const int n = n0 + i, k = k0 + threadIdx.x;
        outT[(size_t)n * K + k] = __float2half_rn(t[threadIdx.x][i]);
    }
}

// ==================== HMMA GEMM ====================
// C[M=2048, N] = (Ahi + Alo)[M,K] @ B[K,N] + bias
// A: [M,K] fp16 K-major (hi & lo); B: pre-transposed [N,K] fp16 K-major.
// CTA tile 128x128, k-tile 64, 3-stage cp.async; 8 warps, warp tile 64x32.
#define GSTAGES 3
#define STG_BYTES 49152        // 16KB Ahi + 16KB Alo + 16KB B
#define GEMM_SMEM (GSTAGES * STG_BYTES)

__device__ __forceinline__ void gemm_load_stage(
    const __half* __restrict__ Ahi, const __half* __restrict__ Alo,
    const __half* __restrict__ Bt,
    int bm, int bn, int K, int kk, uint32_t stg, int tid)
{
    #pragma unroll
    for (int i = 0; i < 4; i++) {
        const int ch = tid + i * 256;
        const int r = ch >> 3, cc = ch & 7;
        const uint32_t off = (uint32_t)(r * 128 + cc * 16);
        const uint32_t sw = SMEM_SWZ(off);
        const size_t asrc = (size_t)(bm + r) * K + kk + cc * 8;
        cp16(stg + sw, Ahi + asrc);
        cp16(stg + 16384 + sw, Alo + asrc);
        cp16(stg + 32768 + sw, Bt + (size_t)(bn + r) * K + kk + cc * 8);
    }
}

template <int MODE>
__global__ void __launch_bounds__(256, 1) gemm_hmma(
    const __half* __restrict__ Ahi, const __half* __restrict__ Alo,
    const __half* __restrict__ Bt, const float* __restrict__ bias,
    int N, int K,
    float* __restrict__ out0, float* __restrict__ outK, float* __restrict__ outV)
{
    extern __shared__ char smem[];
    const uint32_t sb = smem_u32(smem);
    const int tid = threadIdx.x;
    const int bm = blockIdx.x * 128;
    const int bn = blockIdx.y * 128;
    const int wid = tid >> 5, lane = tid & 31;
    const int wm = (wid & 1) * 64;       // warp m offset (2 groups)
    const int wn = (wid >> 1) * 32;      // warp n offset (4 groups)

    // ldmatrix lane geometry
    const int arow = wm + (lane & 15);           // + i*16
    const int achb = lane >> 4;                  // chunk bit for A
    const int brow = wn + (lane & 7) + ((lane & 16) >> 1);   // + j*16
    const int bchb = (lane >> 3) & 1;            // chunk bit for B

    float acc[4][4][4];
    #pragma unroll
    for (int i = 0; i < 4; i++)
        #pragma unroll
        for (int j = 0; j < 4; j++)
            #pragma unroll
            for (int e = 0; e < 4; e++) acc[i][j][e] = 0.f;

    const int T = K >> 6;   // 64-wide k tiles

    // prologue: stages 0,1
    #pragma unroll
    for (int s = 0; s < GSTAGES - 1; s++) {
        gemm_load_stage(Ahi, Alo, Bt, bm, bn, K, s * 64, sb + s * STG_BYTES, tid);
        cp_commit();
    }

    for (int kt = 0; kt < T; kt++) {
        if (kt < T - (GSTAGES - 1)) cp_wait<GSTAGES - 2>(); else cp_wait<0>();
        __syncthreads();

        // prefetch stage kt+2
        if (kt + GSTAGES - 1 < T) {
            const int s = (kt + GSTAGES - 1) % GSTAGES;
            gemm_load_stage(Ahi, Alo, Bt, bm, bn, K, (kt + GSTAGES - 1) * 64,
                            sb + s * STG_BYTES, tid);
            cp_commit();
        }

        const uint32_t stg = sb + (kt % GSTAGES) * STG_BYTES;
        const uint32_t Ah = stg, Al = stg + 16384, Bb = stg + 32768;

        #pragma unroll
        for (int ks = 0; ks < 4; ks++) {
            // B fragments: 2 ldsm.x4 -> 4 n8 tiles
            uint32_t bfr[4][2];
            #pragma unroll
            for (int j = 0; j < 2; j++) {
                const int rr = brow + j * 16;
                const int ch = (ks * 2 + bchb) ^ (rr & 7);
                uint32_t r0, r1, r2, r3;
                LDSM_X4(r0, r1, r2, r3, Bb + (uint32_t)(rr * 128 + ch * 16));
                bfr[j * 2 + 0][0] = r0; bfr[j * 2 + 0][1] = r1;
                bfr[j * 2 + 1][0] = r2; bfr[j * 2 + 1][1] = r3;
            }
            #pragma unroll
            for (int i = 0; i < 4; i++) {
                const int rr = arow + i * 16;
                const int ch = (ks * 2 + achb) ^ (rr & 7);
                const uint32_t aoff = (uint32_t)(rr * 128 + ch * 16);
                uint32_t a0, a1, a2, a3;
                LDSM_X4(a0, a1, a2, a3, Ah + aoff);
                #pragma unroll
                for (int j = 0; j < 4; j++)
                    MMA16816(acc[i][j], a0, a1, a2, a3, bfr[j][0], bfr[j][1]);
                uint32_t l0, l1, l2, l3;
                LDSM_X4(l0, l1, l2, l3, Al + aoff);
                #pragma unroll
                for (int j = 0; j < 4; j++)
                    MMA16816(acc[i][j], l0, l1, l2, l3, bfr[j][0], bfr[j][1]);
            }
        }
    }

    // ---------------- epilogue ----------------
    float* obase;
    int ostride;
    if (MODE == 0) {
        obase = out0 + (size_t)bm * N + bn;
        ostride = N;
    } else {
        const int b = bm >> 10, s0 = bm & 1023;
        const int seg = bn >> 12, h = (bn & 4095) >> 7;
        if (seg == 0)      obase = g_q  + (((size_t)(b * 32 + h)) * 1024 + s0) * 128;
        else if (seg == 1) obase = outK + (((size_t)(b * 32 + h)) * 2048 + s0) * 128;
        else               obase = outV + (((size_t)(b * 32 + h)) * 2048 + s0) * 128;
        ostride = 128;
    }

    const int lr = lane >> 2;            // 0..7
    const int lc2 = (lane & 3) * 2;      // 0,2,4,6
    #pragma unroll
    for (int i = 0; i < 4; i++) {
        #pragma unroll
        for (int j = 0; j < 4; j++) {
            const int c = wn + j * 8 + lc2;
            const float bx = __ldg(bias + bn + c);
            const float by = __ldg(bias + bn + c + 1);
            const int r0 = wm + i * 16 + lr;
            float2 v0 = {acc[i][j][0] + bx, acc[i][j][1] + by};
            float2 v1 = {acc[i][j][2] + bx, acc[i][j][3] + by};
            *(float2*)(obase + (size_t)r0 * ostride + c) = v0;
            *(float2*)(obase + (size_t)(r0 + 8) * ostride + c) = v1;
        }
    }
}

// ==================== Flash attention (causal, fp32) ====================
#define QP 132
#define PP 68

__global__ void __launch_bounds__(256) attn_kernel(
    const float* __restrict__ Kc, const float* __restrict__ Vc)
{
    extern __shared__ float smf[];
    float* sQ = smf;
    float* sK = smf + 64 * QP;
    float* sV = smf + 2 * 64 * QP;
    float* sP = smf + 3 * 64 * QP;

    const int qt = blockIdx.x;
    const int bh = blockIdx.y;
    const int b = bh >> 5;
    const int h = bh & 31;
    const int tid = threadIdx.x;
    const int row = tid >> 2;
    const int cq = tid & 3;

    const float* Qb = g_q + ((size_t)bh * 1024 + (size_t)qt * 64) * 128;
    #pragma unroll
    for (int it = 0; it < 8; it++) {
        const int f4 = tid + it * 256;
        const int rr = f4 >> 5, c4 = (f4 & 31) << 2;
        *(float4*)&sQ[rr * QP + c4] = *(const float4*)(Qb + rr * 128 + c4);
    }

    float o[32];
    #pragma unroll
    for (int i = 0; i < 32; i++) o[i] = 0.f;
    float mrow = -INFINITY, lrow = 0.f;
    const float scale = 0.08838834764831845f;
    const int qglob = qt * 64 + row;

    const float* Kb0 = Kc + (size_t)bh * 2048 * 128;
    const float* Vb0 = Vc + (size_t)bh * 2048 * 128;

    for (int kt = 0; kt <= qt; kt++) {
        __syncthreads();
        const float* Kb = Kb0 + (size_t)kt * 64 * 128;
        const float* Vb = Vb0 + (size_t)kt * 64 * 128;
        #pragma unroll
        for (int it = 0; it < 8; it++) {
            const int f4 = tid + it * 256;
            const int rr = f4 >> 5, c4 = (f4 & 31) << 2;
            *(float4*)&sK[rr * QP + c4] = *(const float4*)(Kb + rr * 128 + c4);
            *(float4*)&sV[rr * QP + c4] = *(const float4*)(Vb + rr * 128 + c4);
        }
        __syncthreads();

        float p[16];
        #pragma unroll
        for (int j = 0; j < 16; j++) p[j] = 0.f;
        #pragma unroll 4
        for (int d = 0; d < 128; d += 4) {
            const float4 qv = *(const float4*)&sQ[row * QP + d];
            #pragma unroll
            for (int j = 0; j < 16; j++) {
                const float4 kv = *(const float4*)&sK[(cq + 4 * j) * QP + d];
                p[j] += qv.x * kv.x + qv.y * kv.y + qv.z * kv.z + qv.w * kv.w;
            }
        }
        float tmax = -INFINITY;
        #pragma unroll
        for (int j = 0; j < 16; j++) {
            const int kg = kt * 64 + cq + 4 * j;
            p[j] = (kg <= qglob) ? p[j] * scale : -INFINITY;
            tmax = fmaxf(tmax, p[j]);
        }
        tmax = fmaxf(tmax, __shfl_xor_sync(0xffffffffu, tmax, 1));
        tmax = fmaxf(tmax, __shfl_xor_sync(0xffffffffu, tmax, 2));
        const float mnew = fmaxf(mrow, tmax);
        const float corr = __expf(mrow - mnew);
        float tsum = 0.f;
        #pragma unroll
        for (int j = 0; j < 16; j++) {
            const float e = __expf(p[j] - mnew);
            p[j] = e; tsum += e;
        }
        tsum += __shfl_xor_sync(0xffffffffu, tsum, 1);
        tsum += __shfl_xor_sync(0xffffffffu, tsum, 2);
        lrow = lrow * corr + tsum;
        mrow = mnew;
        #pragma unroll
        for (int i = 0; i < 32; i++) o[i] *= corr;
        #pragma unroll
        for (int j = 0; j < 16; j++) sP[row * PP + cq + 4 * j] = p[j];
        __syncthreads();

        #pragma unroll 4
        for (int c = 0; c < 64; c++) {
            const float pv = sP[row * PP + c];
            #pragma unroll
            for (int jj = 0; jj < 8; jj++) {
                const float4 vv = *(const float4*)&sV[c * QP + cq * 4 + jj * 16];
                o[jj * 4 + 0] += pv * vv.x;
                o[jj * 4 + 1] += pv * vv.y;
                o[jj * 4 + 2] += pv * vv.z;
                o[jj * 4 + 3] += pv * vv.w;
            }
        }
    }

    const float inv = 1.f / lrow;
    float* Ob = g_attn_out + ((size_t)(b * 1024 + qglob)) * 4096 + h * 128;
    #pragma unroll
    for (int jj = 0; jj < 8; jj++) {
        float4 v4;
        v4.x = o[jj * 4 + 0] * inv; v4.y = o[jj * 4 + 1] * inv;
        v4.z = o[jj * 4 + 2] * inv; v4.w = o[jj * 4 + 3] * inv;
        *(float4*)(Ob + cq * 4 + jj * 16) = v4;
    }
}

// ==================== launch ====================
extern "C" void kernel_launch(void* const* d_in, const int* in_sizes, int n_in,
                              void* d_out, int out_size)
{
    const float* x       = (const float*)d_in[0];
    const float* W_qkv   = (const float*)d_in[2];
    const float* b_qkv   = (const float*)d_in[3];
    const float* W_out   = (const float*)d_in[4];
    const float* b_out   = (const float*)d_in[5];
    const float* cache_k = (const float*)d_in[6];
    const float* cache_v = (const float*)d_in[7];

    float* out  = (float*)d_out;
    float* y    = out;
    float* outK = out + 8388608;
    float* outV = out + 25165824;

    __half *ahi, *alo, *bq, *wo;
    float* attn_ptr;
    cudaGetSymbolAddress((void**)&ahi, g_ahi);
    cudaGetSymbolAddress((void**)&alo, g_alo);
    cudaGetSymbolAddress((void**)&bq, g_bqkv);
    cudaGetSymbolAddress((void**)&wo, g_wout);
    cudaGetSymbolAddress((void**)&attn_ptr, g_attn_out);

    cudaMemcpyAsync(outK, cache_k, (size_t)16777216 * sizeof(float), cudaMemcpyDeviceToDevice, 0);
    cudaMemcpyAsync(outV, cache_v, (size_t)16777216 * sizeof(float), cudaMemcpyDeviceToDevice, 0);

    cudaFuncSetAttribute(gemm_hmma<0>, cudaFuncAttributeMaxDynamicSharedMemorySize, GEMM_SMEM);
    cudaFuncSetAttribute(gemm_hmma<1>, cudaFuncAttributeMaxDynamicSharedMemorySize, GEMM_SMEM);

    // splits
    split_a_kernel<<<8192, 256>>>(x, ahi, alo);
    splitT_kernel<<<dim3(384, 128), dim3(32, 8)>>>(W_qkv, bq, 4096, 12288);
    splitT_kernel<<<dim3(128, 128), dim3(32, 8)>>>(W_out, wo, 4096, 4096);

    // QKV projection (tensor cores) -> g_q / outK / outV
    gemm_hmma<1><<<dim3(16, 96), 256, GEMM_SMEM>>>(ahi, alo, bq, b_qkv, 12288, 4096,
                                                   nullptr, outK, outV);

    // causal flash attention
    const size_t att_smem = (size_t)(3 * 64 * QP + 64 * PP) * sizeof(float);
    cudaFuncSetAttribute(attn_kernel, cudaFuncAttributeMaxDynamicSharedMemorySize, (int)att_smem);
    attn_kernel<<<dim3(16, 64), 256, att_smem>>>(outK, outV);

    // output projection
    split_a_kernel<<<8192, 256>>>(attn_ptr, ahi, alo);
    gemm_hmma<0><<<dim3(16, 32), 256, GEMM_SMEM>>>(ahi, alo, wo, b_out, 4096, 4096,
                                                   y, nullptr, nullptr);
}

// round 5
// speedup vs baseline: 5.3426x; 2.3718x over previous
#include <cuda_runtime.h>
#include <cuda_fp16.h>
#include <math.h>
#include <cstdint>

typedef unsigned long long u64;

// ==================== scratch ====================
__device__ __align__(128) __half g_ah[2048 * 4096];        // fp16(x) / A for QKV
__device__ __align__(128) __half g_aout_h[2048 * 4096];    // fp16 attn out / A for out-proj
__device__ __align__(128) __half g_qh[64 * 1024 * 128];
__device__ __align__(128) __half g_ql[64 * 1024 * 128];
__device__ __align__(128) __half g_kh[64 * 1024 * 128];
__device__ __align__(128) __half g_kl[64 * 1024 * 128];
__device__ __align__(128) __half g_vh[64 * 1024 * 128];
__device__ __align__(128) __half g_vl[64 * 1024 * 128];
__device__ __align__(128) __half g_bqkv[12288 * 4096];     // [N,K] fp16
__device__ __align__(128) __half g_wout[4096 * 4096];      // [N,K] fp16

// ==================== PTX helpers ====================
__device__ __forceinline__ uint32_t smem_u32(const void* p) {
    uint32_t a;
    asm("{ .reg .u64 t; cvta.to.shared.u64 t, %1; cvt.u32.u64 %0, t; }" : "=r"(a) : "l"(p));
    return a;
}
__device__ __forceinline__ uint32_t h2_as_u32(__half2 h) {
    union { __half2 h2; uint32_t u; } cvt;
    cvt.h2 = h;
    return cvt.u;
}
__device__ __forceinline__ void cp16(uint32_t dst, const void* src) {
    asm volatile("cp.async.cg.shared.global [%0], [%1], 16;" :: "r"(dst), "l"(src));
}
__device__ __forceinline__ void cp_commit() { asm volatile("cp.async.commit_group;" ::: "memory"); }
template <int N> __device__ __forceinline__ void cp_wait() { asm volatile("cp.async.wait_group %0;" :: "n"(N) : "memory"); }

#define LDSM_X4(r0, r1, r2, r3, addr) \
    asm volatile("ldmatrix.sync.aligned.m8n8.x4.shared.b16 {%0,%1,%2,%3}, [%4];" \
        : "=r"(r0), "=r"(r1), "=r"(r2), "=r"(r3) : "r"(addr))
#define LDSM_X4_T(r0, r1, r2, r3, addr) \
    asm volatile("ldmatrix.sync.aligned.m8n8.x4.trans.shared.b16 {%0,%1,%2,%3}, [%4];" \
        : "=r"(r0), "=r"(r1), "=r"(r2), "=r"(r3) : "r"(addr))

#define MMA16816(d, a0, a1, a2, a3, b0, b1) \
    asm volatile("mma.sync.aligned.m16n8k16.row.col.f32.f16.f16.f32 " \
        "{%0,%1,%2,%3},{%4,%5,%6,%7},{%8,%9},{%0,%1,%2,%3};" \
        : "+f"((d)[0]), "+f"((d)[1]), "+f"((d)[2]), "+f"((d)[3]) \
        : "r"(a0), "r"(a1), "r"(a2), "r"(a3), "r"(b0), "r"(b1))

#define SMEM_SWZ(off)    ((off) ^ (((off) >> 3) & 0x70))   // 128B rows
#define SMEM_SWZ256(off) ((off) ^ (((off) >> 4) & 0x70))   // 256B rows

// ==================== prep kernels ====================
__global__ void __launch_bounds__(256) convert_h_kernel(const float* __restrict__ in,
                                                        __half* __restrict__ out) {
    const size_t i = (size_t)blockIdx.x * 256 + threadIdx.x;
    float4 v = ((const float4*)in)[i];
    __half2* op = (__half2*)out;
    op[2 * i]     = __floats2half2_rn(v.x, v.y);
    op[2 * i + 1] = __floats2half2_rn(v.z, v.w);
}

// W: [K,N] fp32 -> [N,K] fp16
__global__ void __launch_bounds__(256) splitT_kernel(const float* __restrict__ in,
                                                     __half* __restrict__ outT, int K, int N) {
    __shared__ float t[32][33];
    const int n0 = blockIdx.x * 32, k0 = blockIdx.y * 32;
    for (int i = threadIdx.y; i < 32; i += 8)
        t[i][threadIdx.x] = in[(size_t)(k0 + i) * N + n0 + threadIdx.x];
    __syncthreads();
    for (int i = threadIdx.y; i < 32; i += 8)
        outT[(size_t)(n0 + i) * K + k0 + threadIdx.x] = __float2half_rn(t[threadIdx.x][i]);
}

// ==================== HMMA GEMM (CTA 128x256, warp 64x64) ====================
#define STG_BYTES 49152          // 16KB A + 32KB B
#define GEMM_SMEM (3 * STG_BYTES)

__device__ __forceinline__ void gemm_load_stage(
    const __half* __restrict__ A, const __half* __restrict__ Bt,
    int bm, int bn, int K, int kk, uint32_t stg, int tid)
{
    #pragma unroll
    for (int i = 0; i < 4; i++) {
        const int ch = tid + i * 256;
        const int r = ch >> 3, cc = ch & 7;
        cp16(stg + SMEM_SWZ((uint32_t)(r * 128 + cc * 16)),
             A + (size_t)(bm + r) * K + kk + cc * 8);
    }
    #pragma unroll
    for (int i = 0; i < 8; i++) {
        const int ch = tid + i * 256;
        const int r = ch >> 3, cc = ch & 7;
        cp16(stg + 16384 + SMEM_SWZ((uint32_t)(r * 128 + cc * 16)),
             Bt + (size_t)(bn + r) * K + kk + cc * 8);
    }
}

__device__ __forceinline__ void store_qkv_elem(int row, int col, float a, float b,
                                               float* __restrict__ outK, float* __restrict__ outV) {
    const int bb = row >> 10, s = row & 1023;
    const int seg = col >> 12, w = col & 4095;
    const int h = w >> 7, dd = w & 127;
    const int bh = bb * 32 + h;
    const __half ha = __float2half_rn(a), hb = __float2half_rn(b);
    const __half la = __float2half_rn(a - __half2float(ha));
    const __half lb = __float2half_rn(b - __half2float(hb));
    const __half2 hh = __halves2half2(ha, hb);
    const __half2 ll = __halves2half2(la, lb);
    const size_t i16 = ((size_t)bh * 1024 + s) * 128 + dd;
    if (seg == 0) {
        *(__half2*)(g_qh + i16) = hh; *(__half2*)(g_ql + i16) = ll;
    } else if (seg == 1) {
        *(float2*)(outK + ((size_t)bh * 2048 + s) * 128 + dd) = float2{a, b};
        *(__half2*)(g_kh + i16) = hh; *(__half2*)(g_kl + i16) = ll;
    } else {
        *(float2*)(outV + ((size_t)bh * 2048 + s) * 128 + dd) = float2{a, b};
        *(__half2*)(g_vh + i16) = hh; *(__half2*)(g_vl + i16) = ll;
    }
}

template <int MODE>
__global__ void __launch_bounds__(256, 1) gemm_hmma(
    const __half* __restrict__ A, const __half* __restrict__ Bt,
    const float* __restrict__ bias, int N, int K,
    float* __restrict__ out0, float* __restrict__ outK, float* __restrict__ outV)
{
    extern __shared__ char smem[];
    const uint32_t sb = smem_u32(smem);
    const int tid = threadIdx.x;
    const int bm = blockIdx.x * 128;
    const int bn = blockIdx.y * 256;
    const int wid = tid >> 5, lane = tid & 31;
    const int wm = (wid & 1) * 64;
    const int wn = (wid >> 1) * 64;

    const int arow = wm + (lane & 15);
    const int achb = lane >> 4;
    const int brow = wn + (lane & 7) + ((lane & 16) >> 1);
    const int bchb = (lane >> 3) & 1;

    float acc[4][8][4];
    #pragma unroll
    for (int i = 0; i < 4; i++)
        #pragma unroll
        for (int j = 0; j < 8; j++)
            #pragma unroll
            for (int e = 0; e < 4; e++) acc[i][j][e] = 0.f;

    const int T = K >> 6;

    #pragma unroll
    for (int s = 0; s < 2; s++) {
        gemm_load_stage(A, Bt, bm, bn, K, s * 64, sb + s * STG_BYTES, tid);
        cp_commit();
    }

    for (int kt = 0; kt < T; kt++) {
        if (kt < T - 2) cp_wait<1>(); else cp_wait<0>();
        __syncthreads();

        if (kt + 2 < T) {
            gemm_load_stage(A, Bt, bm, bn, K, (kt + 2) * 64,
                            sb + ((kt + 2) % 3) * STG_BYTES, tid);
            cp_commit();
        }

        const uint32_t stg = sb + (kt % 3) * STG_BYTES;
        const uint32_t Ab = stg, Bb = stg + 16384;

        #pragma unroll
        for (int ks = 0; ks < 4; ks++) {
            uint32_t bfr[8][2];
            #pragma unroll
            for (int j2 = 0; j2 < 4; j2++) {
                const int rr = brow + j2 * 16;
                const int ch = (ks * 2 + bchb) ^ (rr & 7);
                uint32_t r0, r1, r2, r3;
                LDSM_X4(r0, r1, r2, r3, Bb + (uint32_t)(rr * 128 + ch * 16));
                bfr[j2 * 2 + 0][0] = r0; bfr[j2 * 2 + 0][1] = r1;
                bfr[j2 * 2 + 1][0] = r2; bfr[j2 * 2 + 1][1] = r3;
            }
            #pragma unroll
            for (int i = 0; i < 4; i++) {
                const int rr = arow + i * 16;
                const int ch = (ks * 2 + achb) ^ (rr & 7);
                uint32_t a0, a1, a2, a3;
                LDSM_X4(a0, a1, a2, a3, Ab + (uint32_t)(rr * 128 + ch * 16));
                #pragma unroll
                for (int j = 0; j < 8; j++)
                    MMA16816(acc[i][j], a0, a1, a2, a3, bfr[j][0], bfr[j][1]);
            }
        }
    }

    // epilogue
    const int lr = lane >> 2, lc2 = (lane & 3) * 2;
    #pragma unroll
    for (int i = 0; i < 4; i++) {
        #pragma unroll
        for (int j = 0; j < 8; j++) {
            const int c = bn + wn + j * 8 + lc2;
            const float bx = __ldg(bias + c);
            const float by = __ldg(bias + c + 1);
            const int r0 = bm + wm + i * 16 + lr;
            const float v0 = acc[i][j][0] + bx, v1 = acc[i][j][1] + by;
            const float v2 = acc[i][j][2] + bx, v3 = acc[i][j][3] + by;
            if (MODE == 0) {
                *(float2*)(out0 + (size_t)r0 * N + c) = float2{v0, v1};
                *(float2*)(out0 + (size_t)(r0 + 8) * N + c) = float2{v2, v3};
            } else {
                store_qkv_elem(r0, c, v0, v1, outK, outV);
                store_qkv_elem(r0 + 8, c, v2, v3, outK, outV);
            }
        }
    }
}

// ==================== HMMA flash attention ====================
// CTA: 128 q-rows of one (b,h); 8 warps (m16 each); kv-tile 64.
// Split precision: QK = qh*kh + ql*kh + qh*kl ; PV = ph*vh + pl*vh + ph*vl.
#define ATT_QH 0
#define ATT_QL 32768
#define ATT_STG0 65536
#define ATT_STG_SZ 65536   // Kh 16K | Kl 16K | Vh 16K | Vl 16K
#define ATT_SMEM (ATT_STG0 + 2 * ATT_STG_SZ)

__device__ __forceinline__ void attn_load_tile(uint32_t dst, const __half* __restrict__ src,
                                               int tid) {
    // 64 rows x 128 halves (256B rows, swizzled)
    #pragma unroll
    for (int i = 0; i < 4; i++) {
        const int ch = tid + i * 256;
        const int r = ch >> 4, c = ch & 15;
        cp16(dst + SMEM_SWZ256((uint32_t)(r * 256 + c * 16)), src + (size_t)r * 128 + c * 8);
    }
}

__global__ void __launch_bounds__(256, 1) attn_hmma()
{
    extern __shared__ char smem[];
    const uint32_t sb = smem_u32(smem);
    const int qt = blockIdx.x;
    const int bh = blockIdx.y;
    const int b = bh >> 5, h = bh & 31;
    const int tid = threadIdx.x;
    const int wid = tid >> 5, lane = tid & 31;

    const size_t qoff = ((size_t)bh * 1024 + qt * 128) * 128;
    // Q tiles: 128 rows x 128 halves
    #pragma unroll
    for (int i = 0; i < 8; i++) {
        const int ch = tid + i * 256;
        const int r = ch >> 4, c = ch & 15;
        const uint32_t sw = SMEM_SWZ256((uint32_t)(r * 256 + c * 16));
        cp16(sb + ATT_QH + sw, g_qh + qoff + (size_t)r * 128 + c * 8);
        cp16(sb + ATT_QL + sw, g_ql + qoff + (size_t)r * 128 + c * 8);
    }
    cp_commit();

    const int nkt = 2 * qt + 2;
    const size_t kvbase = (size_t)bh * 1024 * 128;

    // preload stage 0
    {
        const uint32_t stg = sb + ATT_STG0;
        attn_load_tile(stg,         g_kh + kvbase, tid);
        attn_load_tile(stg + 16384, g_kl + kvbase, tid);
        attn_load_tile(stg + 32768, g_vh + kvbase, tid);
        attn_load_tile(stg + 49152, g_vl + kvbase, tid);
        cp_commit();
    }

    float o[16][4];
    #pragma unroll
    for (int nt = 0; nt < 16; nt++)
        #pragma unroll
        for (int e = 0; e < 4; e++) o[nt][e] = 0.f;
    float m1 = -INFINITY, m2 = -INFINITY, l1 = 0.f, l2 = 0.f;
    const float scale = 0.08838834764831845f;

    const int row1 = qt * 128 + wid * 16 + (lane >> 2);
    const int row2 = row1 + 8;
    const int wrow_min = qt * 128 + wid * 16;

    // frag addressing
    const int qar = wid * 16 + (lane & 15);
    const int qchb = lane >> 4;
    const int kbr = (lane & 7) + ((lane & 16) >> 1);
    const int kchb = (lane >> 3) & 1;
    const int vkv = lane & 15;
    const int vdc = lane >> 4;

    for (int kt = 0; kt < nkt; kt++) {
        const bool pf = (kt + 1 < nkt);
        if (pf) {
            const uint32_t stg = sb + ATT_STG0 + ((kt + 1) & 1) * ATT_STG_SZ;
            const size_t off = kvbase + (size_t)(kt + 1) * 64 * 128;
            attn_load_tile(stg,         g_kh + off, tid);
            attn_load_tile(stg + 16384, g_kl + off, tid);
            attn_load_tile(stg + 32768, g_vh + off, tid);
            attn_load_tile(stg + 49152, g_vl + off, tid);
            cp_commit();
        }
        if (pf) cp_wait<1>(); else cp_wait<0>();
        __syncthreads();

        const bool active = (kt * 64) <= (wrow_min + 15);
        if (active) {
            const uint32_t stg = sb + ATT_STG0 + (kt & 1) * ATT_STG_SZ;
            const uint32_t Kh = stg, Kl = stg + 16384, Vh = stg + 32768, Vl = stg + 49152;

            float s[8][4];
            #pragma unroll
            for (int nt = 0; nt < 8; nt++)
                #pragma unroll
                for (int e = 0; e < 4; e++) s[nt][e] = 0.f;

            // QK pass 1+2: (qh+ql) * kh
            #pragma unroll
            for (int ks = 0; ks < 8; ks++) {
                uint32_t bfr[8][2];
                #pragma unroll
                for (int j2 = 0; j2 < 4; j2++) {
                    const int rr = kbr + j2 * 16;
                    const int ch = (ks * 2 + kchb) ^ (lane & 7);
                    uint32_t r0, r1, r2, r3;
                    LDSM_X4(r0, r1, r2, r3, Kh + (uint32_t)(rr * 256 + ch * 16));
                    bfr[j2 * 2][0] = r0; bfr[j2 * 2][1] = r1;
                    bfr[j2 * 2 + 1][0] = r2; bfr[j2 * 2 + 1][1] = r3;
                }
                const int ch = (ks * 2 + qchb) ^ (qar & 7);
                uint32_t a0, a1, a2, a3;
                LDSM_X4(a0, a1, a2, a3, sb + ATT_QH + (uint32_t)(qar * 256 + ch * 16));
                #pragma unroll
                for (int j = 0; j < 8; j++) MMA16816(s[j], a0, a1, a2, a3, bfr[j][0], bfr[j][1]);
                LDSM_X4(a0, a1, a2, a3, sb + ATT_QL + (uint32_t)(qar * 256 + ch * 16));
                #pragma unroll
                for (int j = 0; j < 8; j++) MMA16816(s[j], a0, a1, a2, a3, bfr[j][0], bfr[j][1]);
            }
            // QK pass 3: qh * kl
            #pragma unroll
            for (int ks = 0; ks < 8; ks++) {
                uint32_t bfr[8][2];
                #pragma unroll
                for (int j2 = 0; j2 < 4; j2++) {
                    const int rr = kbr + j2 * 16;
                    const int ch = (ks * 2 + kchb) ^ (lane & 7);
                    uint32_t r0, r1, r2, r3;
                    LDSM_X4(r0, r1, r2, r3, Kl + (uint32_t)(rr * 256 + ch * 16));
                    bfr[j2 * 2][0] = r0; bfr[j2 * 2][1] = r1;
                    bfr[j2 * 2 + 1][0] = r2; bfr[j2 * 2 + 1][1] = r3;
                }
                const int ch = (ks * 2 + qchb) ^ (qar & 7);
                uint32_t a0, a1, a2, a3;
                LDSM_X4(a0, a1, a2, a3, sb + ATT_QH + (uint32_t)(qar * 256 + ch * 16));
                #pragma unroll
                for (int j = 0; j < 8; j++) MMA16816(s[j], a0, a1, a2, a3, bfr[j][0], bfr[j][1]);
            }

            // scale + mask + online softmax
            const bool need_mask = (kt * 64 + 63) > wrow_min;
            float mx1 = -INFINITY, mx2 = -INFINITY;
            #pragma unroll
            for (int nt = 0; nt < 8; nt++) {
                const int cg = kt * 64 + nt * 8 + (lane & 3) * 2;
                #pragma unroll
                for (int e = 0; e < 2; e++) {
                    float v = s[nt][e] * scale;
                    if (need_mask && (cg + e > row1)) v = -INFINITY;
                    s[nt][e] = v; mx1 = fmaxf(mx1, v);
                }
                #pragma unroll
                for (int e = 2; e < 4; e++) {
                    float v = s[nt][e] * scale;
                    if (need_mask && (cg + e - 2 > row2)) v = -INFINITY;
                    s[nt][e] = v; mx2 = fmaxf(mx2, v);
                }
            }
            mx1 = fmaxf(mx1, __shfl_xor_sync(0xffffffffu, mx1, 1));
            mx1 = fmaxf(mx1, __shfl_xor_sync(0xffffffffu, mx1, 2));
            mx2 = fmaxf(mx2, __shfl_xor_sync(0xffffffffu, mx2, 1));
            mx2 = fmaxf(mx2, __shfl_xor_sync(0xffffffffu, mx2, 2));
            const float mn1 = fmaxf(m1, mx1), mn2 = fmaxf(m2, mx2);
            const float c1 = __expf(m1 - mn1), c2 = __expf(m2 - mn2);
            m1 = mn1; m2 = mn2;

            uint32_t ph2[8][2], pl2[8][2];
            float ts1 = 0.f, ts2 = 0.f;
            #pragma unroll
            for (int nt = 0; nt < 8; nt++) {
                float p0 = __expf(s[nt][0] - mn1), p1 = __expf(s[nt][1] - mn1);
                float p2 = __expf(s[nt][2] - mn2), p3 = __expf(s[nt][3] - mn2);
                ts1 += p0 + p1; ts2 += p2 + p3;
                __half h0 = __float2half_rn(p0), h1 = __float2half_rn(p1);
                __half h2 = __float2half_rn(p2), h3 = __float2half_rn(p3);
                ph2[nt][0] = h2_as_u32(__halves2half2(h0, h1));
                ph2[nt][1] = h2_as_u32(__halves2half2(h2, h3));
                pl2[nt][0] = h2_as_u32(__floats2half2_rn(p0 - __half2float(h0), p1 - __half2float(h1)));
                pl2[nt][1] = h2_as_u32(__floats2half2_rn(p2 - __half2float(h2), p3 - __half2float(h3)));
            }
            l1 = l1 * c1 + ts1; l2 = l2 * c2 + ts2;
            #pragma unroll
            for (int nt = 0; nt < 16; nt++) {
                o[nt][0] *= c1; o[nt][1] *= c1; o[nt][2] *= c2; o[nt][3] *= c2;
            }

            // PV
            #pragma unroll
            for (int ks = 0; ks < 4; ks++) {
                const uint32_t ah0 = ph2[2 * ks][0], ah1 = ph2[2 * ks][1];
                const uint32_t ah2 = ph2[2 * ks + 1][0], ah3 = ph2[2 * ks + 1][1];
                const uint32_t al0 = pl2[2 * ks][0], al1 = pl2[2 * ks][1];
                const uint32_t al2 = pl2[2 * ks + 1][0], al3 = pl2[2 * ks + 1][1];
                #pragma unroll
                for (int d2 = 0; d2 < 8; d2++) {
                    const int kvr = ks * 16 + vkv;
                    const int ch = (d2 * 2 + vdc) ^ (vkv & 7);
                    const uint32_t va = (uint32_t)(kvr * 256 + ch * 16);
                    uint32_t v0, v1, v2, v3;
                    LDSM_X4_T(v0, v1, v2, v3, Vh + va);
                    MMA16816(o[2 * d2],     ah0, ah1, ah2, ah3, v0, v1);
                    MMA16816(o[2 * d2 + 1], ah0, ah1, ah2, ah3, v2, v3);
                    MMA16816(o[2 * d2],     al0, al1, al2, al3, v0, v1);
                    MMA16816(o[2 * d2 + 1], al0, al1, al2, al3, v2, v3);
                    LDSM_X4_T(v0, v1, v2, v3, Vl + va);
                    MMA16816(o[2 * d2],     ah0, ah1, ah2, ah3, v0, v1);
                    MMA16816(o[2 * d2 + 1], ah0, ah1, ah2, ah3, v2, v3);
                }
            }
        }
        __syncthreads();
    }

    l1 += __shfl_xor_sync(0xffffffffu, l1, 1);
    l1 += __shfl_xor_sync(0xffffffffu, l1, 2);
    l2 += __shfl_xor_sync(0xffffffffu, l2, 1);
    l2 += __shfl_xor_sync(0xffffffffu, l2, 2);
    const float i1 = 1.f / l1, i2 = 1.f / l2;

    __half* outp = g_aout_h;
    #pragma unroll
    for (int nt = 0; nt < 16; nt++) {
        const int col = h * 128 + nt * 8 + (lane & 3) * 2;
        *(__half2*)(outp + (size_t)(b * 1024 + row1) * 4096 + col) =
            __floats2half2_rn(o[nt][0] * i1, o[nt][1] * i1);
        *(__half2*)(outp + (size_t)(b * 1024 + row2) * 4096 + col) =
            __floats2half2_rn(o[nt][2] * i2, o[nt][3] * i2);
    }
}

// ==================== launch ====================
extern "C" void kernel_launch(void* const* d_in, const int* in_sizes, int n_in,
                              void* d_out, int out_size)
{
    const float* x       = (const float*)d_in[0];
    const float* W_qkv   = (const float*)d_in[2];
    const float* b_qkv   = (const float*)d_in[3];
    const float* W_out   = (const float*)d_in[4];
    const float* b_out   = (const float*)d_in[5];
    const float* cache_k = (const float*)d_in[6];
    const float* cache_v = (const float*)d_in[7];

    float* out  = (float*)d_out;
    float* y    = out;
    float* outK = out + 8388608;
    float* outV = out + 25165824;

    __half *ah, *aout, *bq, *wo;
    cudaGetSymbolAddress((void**)&ah, g_ah);
    cudaGetSymbolAddress((void**)&aout, g_aout_h);
    cudaGetSymbolAddress((void**)&bq, g_bqkv);
    cudaGetSymbolAddress((void**)&wo, g_wout);

    cudaMemcpyAsync(outK, cache_k, (size_t)16777216 * sizeof(float), cudaMemcpyDeviceToDevice, 0);
    cudaMemcpyAsync(outV, cache_v, (size_t)16777216 * sizeof(float), cudaMemcpyDeviceToDevice, 0);

    cudaFuncSetAttribute(gemm_hmma<0>, cudaFuncAttributeMaxDynamicSharedMemorySize, GEMM_SMEM);
    cudaFuncSetAttribute(gemm_hmma<1>, cudaFuncAttributeMaxDynamicSharedMemorySize, GEMM_SMEM);
    cudaFuncSetAttribute(attn_hmma, cudaFuncAttributeMaxDynamicSharedMemorySize, ATT_SMEM);

    convert_h_kernel<<<8192, 256>>>(x, ah);
    splitT_kernel<<<dim3(384, 128), dim3(32, 8)>>>(W_qkv, bq, 4096, 12288);
    splitT_kernel<<<dim3(128, 128), dim3(32, 8)>>>(W_out, wo, 4096, 4096);

    gemm_hmma<1><<<dim3(16, 48), 256, GEMM_SMEM>>>(ah, bq, b_qkv, 12288, 4096,
                                                   nullptr, outK, outV);

    attn_hmma<<<dim3(8, 64), 256, ATT_SMEM>>>();

    gemm_hmma<0><<<dim3(16, 16), 256, GEMM_SMEM>>>(aout, wo, b_out, 4096, 4096,
                                                   y, nullptr, nullptr);
}

// round 6
// speedup vs baseline: 5.6759x; 1.0624x over previous
#include <cuda_runtime.h>
#include <cuda_fp16.h>
#include <math.h>
#include <cstdint>

typedef unsigned long long u64;

// ==================== scratch ====================
__device__ __align__(128) __half g_ah[2048 * 4096];        // fp16(x) / A for QKV
__device__ __align__(128) __half g_aout_h[2048 * 4096];    // fp16 attn out / A for out-proj
__device__ __align__(128) __half g_qh[64 * 1024 * 128];
__device__ __align__(128) __half g_ql[64 * 1024 * 128];
__device__ __align__(128) __half g_kh[64 * 1024 * 128];
__device__ __align__(128) __half g_kl[64 * 1024 * 128];
__device__ __align__(128) __half g_vh[64 * 1024 * 128];
__device__ __align__(128) __half g_vl[64 * 1024 * 128];
__device__ __align__(128) __half g_bqkv[12288 * 4096];     // [N,K] fp16
__device__ __align__(128) __half g_wout[4096 * 4096];      // [N,K] fp16

// ==================== PTX helpers ====================
__device__ __forceinline__ uint32_t smem_u32(const void* p) {
    uint32_t a;
    asm("{ .reg .u64 t; cvta.to.shared.u64 t, %1; cvt.u32.u64 %0, t; }" : "=r"(a) : "l"(p));
    return a;
}
__device__ __forceinline__ uint32_t h2_as_u32(__half2 h) {
    union { __half2 h2; uint32_t u; } cvt;
    cvt.h2 = h;
    return cvt.u;
}
__device__ __forceinline__ void cp16(uint32_t dst, const void* src) {
    asm volatile("cp.async.cg.shared.global [%0], [%1], 16;" :: "r"(dst), "l"(src));
}
__device__ __forceinline__ void cp_commit() { asm volatile("cp.async.commit_group;" ::: "memory"); }
template <int N> __device__ __forceinline__ void cp_wait() { asm volatile("cp.async.wait_group %0;" :: "n"(N) : "memory"); }

#define LDSM_X4(r0, r1, r2, r3, addr) \
    asm volatile("ldmatrix.sync.aligned.m8n8.x4.shared.b16 {%0,%1,%2,%3}, [%4];" \
        : "=r"(r0), "=r"(r1), "=r"(r2), "=r"(r3) : "r"(addr))
#define LDSM_X4_T(r0, r1, r2, r3, addr) \
    asm volatile("ldmatrix.sync.aligned.m8n8.x4.trans.shared.b16 {%0,%1,%2,%3}, [%4];" \
        : "=r"(r0), "=r"(r1), "=r"(r2), "=r"(r3) : "r"(addr))

#define MMA16816(d, a0, a1, a2, a3, b0, b1) \
    asm volatile("mma.sync.aligned.m16n8k16.row.col.f32.f16.f16.f32 " \
        "{%0,%1,%2,%3},{%4,%5,%6,%7},{%8,%9},{%0,%1,%2,%3};" \
        : "+f"((d)[0]), "+f"((d)[1]), "+f"((d)[2]), "+f"((d)[3]) \
        : "r"(a0), "r"(a1), "r"(a2), "r"(a3), "r"(b0), "r"(b1))

#define SMEM_SWZ(off)    ((off) ^ (((off) >> 3) & 0x70))   // 128B rows
#define SMEM_SWZ256(off) ((off) ^ (((off) >> 4) & 0x70))   // 256B rows

// ==================== prep kernels ====================
__global__ void __launch_bounds__(256) convert_h_kernel(const float* __restrict__ in,
                                                        __half* __restrict__ out) {
    const size_t i = (size_t)blockIdx.x * 256 + threadIdx.x;
    float4 v = ((const float4*)in)[i];
    __half2* op = (__half2*)out;
    op[2 * i]     = __floats2half2_rn(v.x, v.y);
    op[2 * i + 1] = __floats2half2_rn(v.z, v.w);
}

// W: [K,N] fp32 -> [N,K] fp16, half2 stores. block (32,8), tile 64k x 32n.
__global__ void __launch_bounds__(256) splitT_kernel(const float* __restrict__ in,
                                                     __half* __restrict__ outT, int K, int N) {
    __shared__ float t[64][33];
    const int n0 = blockIdx.x * 32, k0 = blockIdx.y * 64;
    const int tx = threadIdx.x, ty = threadIdx.y;
    #pragma unroll
    for (int i = ty; i < 64; i += 8)
        t[i][tx] = in[(size_t)(k0 + i) * N + n0 + tx];
    __syncthreads();
    #pragma unroll
    for (int i = ty; i < 32; i += 8) {
        const __half2 hv = __floats2half2_rn(t[tx * 2][i], t[tx * 2 + 1][i]);
        *(__half2*)(outT + (size_t)(n0 + i) * K + k0 + tx * 2) = hv;
    }
}

// ==================== HMMA GEMM (CTA 128x128, warp 64x32, 2 CTAs/SM) ====================
#define STG_BYTES 32768          // 16KB A + 16KB B
#define GEMM_SMEM (3 * STG_BYTES)

__device__ __forceinline__ void gemm_load_stage(
    const __half* __restrict__ A, const __half* __restrict__ Bt,
    int bm, int bn, int K, int kk, uint32_t stg, int tid)
{
    #pragma unroll
    for (int i = 0; i < 4; i++) {
        const int ch = tid + i * 256;
        const int r = ch >> 3, cc = ch & 7;
        cp16(stg + SMEM_SWZ((uint32_t)(r * 128 + cc * 16)),
             A + (size_t)(bm + r) * K + kk + cc * 8);
    }
    #pragma unroll
    for (int i = 0; i < 4; i++) {
        const int ch = tid + i * 256;
        const int r = ch >> 3, cc = ch & 7;
        cp16(stg + 16384 + SMEM_SWZ((uint32_t)(r * 128 + cc * 16)),
             Bt + (size_t)(bn + r) * K + kk + cc * 8);
    }
}

__device__ __forceinline__ void store_qkv_elem(int row, int col, float a, float b,
                                               float* __restrict__ outK, float* __restrict__ outV) {
    const int bb = row >> 10, s = row & 1023;
    const int seg = col >> 12, w = col & 4095;
    const int h = w >> 7, dd = w & 127;
    const int bh = bb * 32 + h;
    const __half ha = __float2half_rn(a), hb = __float2half_rn(b);
    const __half la = __float2half_rn(a - __half2float(ha));
    const __half lb = __float2half_rn(b - __half2float(hb));
    const __half2 hh = __halves2half2(ha, hb);
    const __half2 ll = __halves2half2(la, lb);
    const size_t i16 = ((size_t)bh * 1024 + s) * 128 + dd;
    if (seg == 0) {
        *(__half2*)(g_qh + i16) = hh; *(__half2*)(g_ql + i16) = ll;
    } else if (seg == 1) {
        *(float2*)(outK + ((size_t)bh * 2048 + s) * 128 + dd) = float2{a, b};
        *(__half2*)(g_kh + i16) = hh; *(__half2*)(g_kl + i16) = ll;
    } else {
        *(float2*)(outV + ((size_t)bh * 2048 + s) * 128 + dd) = float2{a, b};
        *(__half2*)(g_vh + i16) = hh; *(__half2*)(g_vl + i16) = ll;
    }
}

template <int MODE>
__global__ void __launch_bounds__(256, 2) gemm_hmma(
    const __half* __restrict__ A, const __half* __restrict__ Bt,
    const float* __restrict__ bias, int N, int K,
    float* __restrict__ out0, float* __restrict__ outK, float* __restrict__ outV)
{
    extern __shared__ char smem[];
    const uint32_t sb = smem_u32(smem);
    const int tid = threadIdx.x;
    const int bm = blockIdx.x * 128;
    const int bn = blockIdx.y * 128;
    const int wid = tid >> 5, lane = tid & 31;
    const int wm = (wid & 1) * 64;
    const int wn = (wid >> 1) * 32;

    const int arow = wm + (lane & 15);
    const int achb = lane >> 4;
    const int brow = wn + (lane & 7) + ((lane & 16) >> 1);
    const int bchb = (lane >> 3) & 1;

    float acc[4][4][4];
    #pragma unroll
    for (int i = 0; i < 4; i++)
        #pragma unroll
        for (int j = 0; j < 4; j++)
            #pragma unroll
            for (int e = 0; e < 4; e++) acc[i][j][e] = 0.f;

    const int T = K >> 6;

    #pragma unroll
    for (int s = 0; s < 2; s++) {
        gemm_load_stage(A, Bt, bm, bn, K, s * 64, sb + s * STG_BYTES, tid);
        cp_commit();
    }

    for (int kt = 0; kt < T; kt++) {
        if (kt < T - 2) cp_wait<1>(); else cp_wait<0>();
        __syncthreads();

        if (kt + 2 < T) {
            gemm_load_stage(A, Bt, bm, bn, K, (kt + 2) * 64,
                            sb + ((kt + 2) % 3) * STG_BYTES, tid);
            cp_commit();
        }

        const uint32_t stg = sb + (kt % 3) * STG_BYTES;
        const uint32_t Ab = stg, Bb = stg + 16384;

        #pragma unroll
        for (int ks = 0; ks < 4; ks++) {
            uint32_t bfr[4][2];
            #pragma unroll
            for (int j2 = 0; j2 < 2; j2++) {
                const int rr = brow + j2 * 16;
                const int ch = (ks * 2 + bchb) ^ (rr & 7);
                uint32_t r0, r1, r2, r3;
                LDSM_X4(r0, r1, r2, r3, Bb + (uint32_t)(rr * 128 + ch * 16));
                bfr[j2 * 2 + 0][0] = r0; bfr[j2 * 2 + 0][1] = r1;
                bfr[j2 * 2 + 1][0] = r2; bfr[j2 * 2 + 1][1] = r3;
            }
            #pragma unroll
            for (int i = 0; i < 4; i++) {
                const int rr = arow + i * 16;
                const int ch = (ks * 2 + achb) ^ (rr & 7);
                uint32_t a0, a1, a2, a3;
                LDSM_X4(a0, a1, a2, a3, Ab + (uint32_t)(rr * 128 + ch * 16));
                #pragma unroll
                for (int j = 0; j < 4; j++)
                    MMA16816(acc[i][j], a0, a1, a2, a3, bfr[j][0], bfr[j][1]);
            }
        }
    }

    // epilogue
    const int lr = lane >> 2, lc2 = (lane & 3) * 2;
    #pragma unroll
    for (int i = 0; i < 4; i++) {
        #pragma unroll
        for (int j = 0; j < 4; j++) {
            const int c = bn + wn + j * 8 + lc2;
            const float bx = __ldg(bias + c);
            const float by = __ldg(bias + c + 1);
            const int r0 = bm + wm + i * 16 + lr;
            const float v0 = acc[i][j][0] + bx, v1 = acc[i][j][1] + by;
            const float v2 = acc[i][j][2] + bx, v3 = acc[i][j][3] + by;
            if (MODE == 0) {
                *(float2*)(out0 + (size_t)r0 * N + c) = float2{v0, v1};
                *(float2*)(out0 + (size_t)(r0 + 8) * N + c) = float2{v2, v3};
            } else {
                store_qkv_elem(r0, c, v0, v1, outK, outV);
                store_qkv_elem(r0 + 8, c, v2, v3, outK, outV);
            }
        }
    }
}

// ==================== HMMA flash attention ====================
// CTA: 128 q-rows of one (b,h); 8 warps (m16 each); kv-tile 64.
// Split precision: QK = qh*kh + ql*kh + qh*kl ; PV = ph*vh + pl*vh + ph*vl.
#define ATT_QH 0
#define ATT_QL 32768
#define ATT_STG0 65536
#define ATT_STG_SZ 65536   // Kh 16K | Kl 16K | Vh 16K | Vl 16K
#define ATT_SMEM (ATT_STG0 + 2 * ATT_STG_SZ)

__device__ __forceinline__ void attn_load_tile(uint32_t dst, const __half* __restrict__ src,
                                               int tid) {
    // 64 rows x 128 halves (256B rows, swizzled)
    #pragma unroll
    for (int i = 0; i < 4; i++) {
        const int ch = tid + i * 256;
        const int r = ch >> 4, c = ch & 15;
        cp16(dst + SMEM_SWZ256((uint32_t)(r * 256 + c * 16)), src + (size_t)r * 128 + c * 8);
    }
}

__global__ void __launch_bounds__(256, 1) attn_hmma()
{
    extern __shared__ char smem[];
    const uint32_t sb = smem_u32(smem);
    const int qt = blockIdx.x;
    const int bh = blockIdx.y;
    const int b = bh >> 5, h = bh & 31;
    const int tid = threadIdx.x;
    const int wid = tid >> 5, lane = tid & 31;

    const size_t qoff = ((size_t)bh * 1024 + qt * 128) * 128;
    // Q tiles: 128 rows x 128 halves
    #pragma unroll
    for (int i = 0; i < 8; i++) {
        const int ch = tid + i * 256;
        const int r = ch >> 4, c = ch & 15;
        const uint32_t sw = SMEM_SWZ256((uint32_t)(r * 256 + c * 16));
        cp16(sb + ATT_QH + sw, g_qh + qoff + (size_t)r * 128 + c * 8);
        cp16(sb + ATT_QL + sw, g_ql + qoff + (size_t)r * 128 + c * 8);
    }
    cp_commit();

    const int nkt = 2 * qt + 2;
    const size_t kvbase = (size_t)bh * 1024 * 128;

    // preload stage 0
    {
        const uint32_t stg = sb + ATT_STG0;
        attn_load_tile(stg,         g_kh + kvbase, tid);
        attn_load_tile(stg + 16384, g_kl + kvbase, tid);
        attn_load_tile(stg + 32768, g_vh + kvbase, tid);
        attn_load_tile(stg + 49152, g_vl + kvbase, tid);
        cp_commit();
    }

    float o[16][4];
    #pragma unroll
    for (int nt = 0; nt < 16; nt++)
        #pragma unroll
        for (int e = 0; e < 4; e++) o[nt][e] = 0.f;
    float m1 = -INFINITY, m2 = -INFINITY, l1 = 0.f, l2 = 0.f;
    const float scale = 0.08838834764831845f;

    const int row1 = qt * 128 + wid * 16 + (lane >> 2);
    const int row2 = row1 + 8;
    const int wrow_min = qt * 128 + wid * 16;

    // frag addressing
    const int qar = wid * 16 + (lane & 15);
    const int qchb = lane >> 4;
    const int kbr = (lane & 7) + ((lane & 16) >> 1);
    const int kchb = (lane >> 3) & 1;
    const int vkv = lane & 15;
    const int vdc = lane >> 4;

    for (int kt = 0; kt < nkt; kt++) {
        const bool pf = (kt + 1 < nkt);
        if (pf) {
            const uint32_t stg = sb + ATT_STG0 + ((kt + 1) & 1) * ATT_STG_SZ;
            const size_t off = kvbase + (size_t)(kt + 1) * 64 * 128;
            attn_load_tile(stg,         g_kh + off, tid);
            attn_load_tile(stg + 16384, g_kl + off, tid);
            attn_load_tile(stg + 32768, g_vh + off, tid);
            attn_load_tile(stg + 49152, g_vl + off, tid);
            cp_commit();
        }
        if (pf) cp_wait<1>(); else cp_wait<0>();
        __syncthreads();

        const bool active = (kt * 64) <= (wrow_min + 15);
        if (active) {
            const uint32_t stg = sb + ATT_STG0 + (kt & 1) * ATT_STG_SZ;
            const uint32_t Kh = stg, Kl = stg + 16384, Vh = stg + 32768, Vl = stg + 49152;

            float s[8][4];
            #pragma unroll
            for (int nt = 0; nt < 8; nt++)
                #pragma unroll
                for (int e = 0; e < 4; e++) s[nt][e] = 0.f;

            // QK pass 1+2: (qh+ql) * kh
            #pragma unroll
            for (int ks = 0; ks < 8; ks++) {
                uint32_t bfr[8][2];
                #pragma unroll
                for (int j2 = 0; j2 < 4; j2++) {
                    const int rr = kbr + j2 * 16;
                    const int ch = (ks * 2 + kchb) ^ (lane & 7);
                    uint32_t r0, r1, r2, r3;
                    LDSM_X4(r0, r1, r2, r3, Kh + (uint32_t)(rr * 256 + ch * 16));
                    bfr[j2 * 2][0] = r0; bfr[j2 * 2][1] = r1;
                    bfr[j2 * 2 + 1][0] = r2; bfr[j2 * 2 + 1][1] = r3;
                }
                const int ch = (ks * 2 + qchb) ^ (qar & 7);
                uint32_t a0, a1, a2, a3;
                LDSM_X4(a0, a1, a2, a3, sb + ATT_QH + (uint32_t)(qar * 256 + ch * 16));
                #pragma unroll
                for (int j = 0; j < 8; j++) MMA16816(s[j], a0, a1, a2, a3, bfr[j][0], bfr[j][1]);
                LDSM_X4(a0, a1, a2, a3, sb + ATT_QL + (uint32_t)(qar * 256 + ch * 16));
                #pragma unroll
                for (int j = 0; j < 8; j++) MMA16816(s[j], a0, a1, a2, a3, bfr[j][0], bfr[j][1]);
            }
            // QK pass 3: qh * kl
            #pragma unroll
            for (int ks = 0; ks < 8; ks++) {
                uint32_t bfr[8][2];
                #pragma unroll
                for (int j2 = 0; j2 < 4; j2++) {
                    const int rr = kbr + j2 * 16;
                    const int ch = (ks * 2 + kchb) ^ (lane & 7);
                    uint32_t r0, r1, r2, r3;
                    LDSM_X4(r0, r1, r2, r3, Kl + (uint32_t)(rr * 256 + ch * 16));
                    bfr[j2 * 2][0] = r0; bfr[j2 * 2][1] = r1;
                    bfr[j2 * 2 + 1][0] = r2; bfr[j2 * 2 + 1][1] = r3;
                }
                const int ch = (ks * 2 + qchb) ^ (qar & 7);
                uint32_t a0, a1, a2, a3;
                LDSM_X4(a0, a1, a2, a3, sb + ATT_QH + (uint32_t)(qar * 256 + ch * 16));
                #pragma unroll
                for (int j = 0; j < 8; j++) MMA16816(s[j], a0, a1, a2, a3, bfr[j][0], bfr[j][1]);
            }

            // scale + mask + online softmax
            const bool need_mask = (kt * 64 + 63) > wrow_min;
            float mx1 = -INFINITY, mx2 = -INFINITY;
            #pragma unroll
            for (int nt = 0; nt < 8; nt++) {
                const int cg = kt * 64 + nt * 8 + (lane & 3) * 2;
                #pragma unroll
                for (int e = 0; e < 2; e++) {
                    float v = s[nt][e] * scale;
                    if (need_mask && (cg + e > row1)) v = -INFINITY;
                    s[nt][e] = v; mx1 = fmaxf(mx1, v);
                }
                #pragma unroll
                for (int e = 2; e < 4; e++) {
                    float v = s[nt][e] * scale;
                    if (need_mask && (cg + e - 2 > row2)) v = -INFINITY;
                    s[nt][e] = v; mx2 = fmaxf(mx2, v);
                }
            }
            mx1 = fmaxf(mx1, __shfl_xor_sync(0xffffffffu, mx1, 1));
            mx1 = fmaxf(mx1, __shfl_xor_sync(0xffffffffu, mx1, 2));
            mx2 = fmaxf(mx2, __shfl_xor_sync(0xffffffffu, mx2, 1));
            mx2 = fmaxf(mx2, __shfl_xor_sync(0xffffffffu, mx2, 2));
            const float mn1 = fmaxf(m1, mx1), mn2 = fmaxf(m2, mx2);
            const float c1 = __expf(m1 - mn1), c2 = __expf(m2 - mn2);
            m1 = mn1; m2 = mn2;

            uint32_t ph2[8][2], pl2[8][2];
            float ts1 = 0.f, ts2 = 0.f;
            #pragma unroll
            for (int nt = 0; nt < 8; nt++) {
                float p0 = __expf(s[nt][0] - mn1), p1 = __expf(s[nt][1] - mn1);
                float p2 = __expf(s[nt][2] - mn2), p3 = __expf(s[nt][3] - mn2);
                ts1 += p0 + p1; ts2 += p2 + p3;
                __half h0 = __float2half_rn(p0), h1 = __float2half_rn(p1);
                __half h2 = __float2half_rn(p2), h3 = __float2half_rn(p3);
                ph2[nt][0] = h2_as_u32(__halves2half2(h0, h1));
                ph2[nt][1] = h2_as_u32(__halves2half2(h2, h3));
                pl2[nt][0] = h2_as_u32(__floats2half2_rn(p0 - __half2float(h0), p1 - __half2float(h1)));
                pl2[nt][1] = h2_as_u32(__floats2half2_rn(p2 - __half2float(h2), p3 - __half2float(h3)));
            }
            l1 = l1 * c1 + ts1; l2 = l2 * c2 + ts2;
            #pragma unroll
            for (int nt = 0; nt < 16; nt++) {
                o[nt][0] *= c1; o[nt][1] *= c1; o[nt][2] *= c2; o[nt][3] *= c2;
            }

            // PV
            #pragma unroll
            for (int ks = 0; ks < 4; ks++) {
                const uint32_t ah0 = ph2[2 * ks][0], ah1 = ph2[2 * ks][1];
                const uint32_t ah2 = ph2[2 * ks + 1][0], ah3 = ph2[2 * ks + 1][1];
                const uint32_t al0 = pl2[2 * ks][0], al1 = pl2[2 * ks][1];
                const uint32_t al2 = pl2[2 * ks + 1][0], al3 = pl2[2 * ks + 1][1];
                #pragma unroll
                for (int d2 = 0; d2 < 8; d2++) {
                    const int kvr = ks * 16 + vkv;
                    const int ch = (d2 * 2 + vdc) ^ (vkv & 7);
                    const uint32_t va = (uint32_t)(kvr * 256 + ch * 16);
                    uint32_t v0, v1, v2, v3;
                    LDSM_X4_T(v0, v1, v2, v3, Vh + va);
                    MMA16816(o[2 * d2],     ah0, ah1, ah2, ah3, v0, v1);
                    MMA16816(o[2 * d2 + 1], ah0, ah1, ah2, ah3, v2, v3);
                    MMA16816(o[2 * d2],     al0, al1, al2, al3, v0, v1);
                    MMA16816(o[2 * d2 + 1], al0, al1, al2, al3, v2, v3);
                    LDSM_X4_T(v0, v1, v2, v3, Vl + va);
                    MMA16816(o[2 * d2],     ah0, ah1, ah2, ah3, v0, v1);
                    MMA16816(o[2 * d2 + 1], ah0, ah1, ah2, ah3, v2, v3);
                }
            }
        }
        __syncthreads();
    }

    l1 += __shfl_xor_sync(0xffffffffu, l1, 1);
    l1 += __shfl_xor_sync(0xffffffffu, l1, 2);
    l2 += __shfl_xor_sync(0xffffffffu, l2, 1);
    l2 += __shfl_xor_sync(0xffffffffu, l2, 2);
    const float i1 = 1.f / l1, i2 = 1.f / l2;

    __half* outp = g_aout_h;
    #pragma unroll
    for (int nt = 0; nt < 16; nt++) {
        const int col = h * 128 + nt * 8 + (lane & 3) * 2;
        *(__half2*)(outp + (size_t)(b * 1024 + row1) * 4096 + col) =
            __floats2half2_rn(o[nt][0] * i1, o[nt][1] * i1);
        *(__half2*)(outp + (size_t)(b * 1024 + row2) * 4096 + col) =
            __floats2half2_rn(o[nt][2] * i2, o[nt][3] * i2);
    }
}

// ==================== launch ====================
extern "C" void kernel_launch(void* const* d_in, const int* in_sizes, int n_in,
                              void* d_out, int out_size)
{
    const float* x       = (const float*)d_in[0];
    const float* W_qkv   = (const float*)d_in[2];
    const float* b_qkv   = (const float*)d_in[3];
    const float* W_out   = (const float*)d_in[4];
    const float* b_out   = (const float*)d_in[5];
    const float* cache_k = (const float*)d_in[6];
    const float* cache_v = (const float*)d_in[7];

    float* out  = (float*)d_out;
    float* y    = out;
    float* outK = out + 8388608;
    float* outV = out + 25165824;

    __half *ah, *aout, *bq, *wo;
    cudaGetSymbolAddress((void**)&ah, g_ah);
    cudaGetSymbolAddress((void**)&aout, g_aout_h);
    cudaGetSymbolAddress((void**)&bq, g_bqkv);
    cudaGetSymbolAddress((void**)&wo, g_wout);

    // tail-only cache preservation: slots [1024,2048) per (b,h); slots < 1024
    // are fully overwritten by the QKV epilogue.
    const size_t pitch = (size_t)2048 * 128 * sizeof(float);   // per-bh stride
    const size_t width = (size_t)1024 * 128 * sizeof(float);   // tail bytes
    cudaMemcpy2DAsync(outK + (size_t)1024 * 128, pitch,
                      cache_k + (size_t)1024 * 128, pitch, width, 64,
                      cudaMemcpyDeviceToDevice, 0);
    cudaMemcpy2DAsync(outV + (size_t)1024 * 128, pitch,
                      cache_v + (size_t)1024 * 128, pitch, width, 64,
                      cudaMemcpyDeviceToDevice, 0);

    cudaFuncSetAttribute(gemm_hmma<0>, cudaFuncAttributeMaxDynamicSharedMemorySize, GEMM_SMEM);
    cudaFuncSetAttribute(gemm_hmma<1>, cudaFuncAttributeMaxDynamicSharedMemorySize, GEMM_SMEM);
    cudaFuncSetAttribute(attn_hmma, cudaFuncAttributeMaxDynamicSharedMemorySize, ATT_SMEM);

    convert_h_kernel<<<8192, 256>>>(x, ah);
    splitT_kernel<<<dim3(384, 64), dim3(32, 8)>>>(W_qkv, bq, 4096, 12288);
    splitT_kernel<<<dim3(128, 64), dim3(32, 8)>>>(W_out, wo, 4096, 4096);

    gemm_hmma<1><<<dim3(16, 96), 256, GEMM_SMEM>>>(ah, bq, b_qkv, 12288, 4096,
                                                   nullptr, outK, outV);

    attn_hmma<<<dim3(8, 64), 256, ATT_SMEM>>>();

    gemm_hmma<0><<<dim3(16, 32), 256, GEMM_SMEM>>>(aout, wo, b_out, 4096, 4096,
                                                   y, nullptr, nullptr);
}

// round 7
// speedup vs baseline: 5.9550x; 1.0492x over previous
#include <cuda_runtime.h>
#include <cuda_fp16.h>
#include <math.h>
#include <cstdint>

typedef unsigned long long u64;

// ==================== scratch ====================
__device__ __align__(128) __half g_ah[2048 * 4096];        // fp16(x) / A for QKV
__device__ __align__(128) __half g_aout_h[2048 * 4096];    // fp16 attn out / A for out-proj
__device__ __align__(128) __half g_qh[64 * 1024 * 128];
__device__ __align__(128) __half g_ql[64 * 1024 * 128];
__device__ __align__(128) __half g_kh[64 * 1024 * 128];
__device__ __align__(128) __half g_kl[64 * 1024 * 128];
__device__ __align__(128) __half g_vh[64 * 1024 * 128];
__device__ __align__(128) __half g_bqkv[12288 * 4096];     // [N,K] fp16
__device__ __align__(128) __half g_wout[4096 * 4096];      // [N,K] fp16

// ==================== PTX helpers ====================
__device__ __forceinline__ uint32_t smem_u32(const void* p) {
    uint32_t a;
    asm("{ .reg .u64 t; cvta.to.shared.u64 t, %1; cvt.u32.u64 %0, t; }" : "=r"(a) : "l"(p));
    return a;
}
__device__ __forceinline__ uint32_t h2_as_u32(__half2 h) {
    union { __half2 h2; uint32_t u; } cvt;
    cvt.h2 = h;
    return cvt.u;
}
__device__ __forceinline__ void cp16(uint32_t dst, const void* src) {
    asm volatile("cp.async.cg.shared.global [%0], [%1], 16;" :: "r"(dst), "l"(src));
}
__device__ __forceinline__ void cp_commit() { asm volatile("cp.async.commit_group;" ::: "memory"); }
template <int N> __device__ __forceinline__ void cp_wait() { asm volatile("cp.async.wait_group %0;" :: "n"(N) : "memory"); }

#define LDSM_X4(r0, r1, r2, r3, addr) \
    asm volatile("ldmatrix.sync.aligned.m8n8.x4.shared.b16 {%0,%1,%2,%3}, [%4];" \
        : "=r"(r0), "=r"(r1), "=r"(r2), "=r"(r3) : "r"(addr))
#define LDSM_X4_T(r0, r1, r2, r3, addr) \
    asm volatile("ldmatrix.sync.aligned.m8n8.x4.trans.shared.b16 {%0,%1,%2,%3}, [%4];" \
        : "=r"(r0), "=r"(r1), "=r"(r2), "=r"(r3) : "r"(addr))

#define MMA16816(d, a0, a1, a2, a3, b0, b1) \
    asm volatile("mma.sync.aligned.m16n8k16.row.col.f32.f16.f16.f32 " \
        "{%0,%1,%2,%3},{%4,%5,%6,%7},{%8,%9},{%0,%1,%2,%3};" \
        : "+f"((d)[0]), "+f"((d)[1]), "+f"((d)[2]), "+f"((d)[3]) \
        : "r"(a0), "r"(a1), "r"(a2), "r"(a3), "r"(b0), "r"(b1))

#define SMEM_SWZ(off)    ((off) ^ (((off) >> 3) & 0x70))   // 128B rows
#define SMEM_SWZ256(off) ((off) ^ (((off) >> 4) & 0x70))   // 256B rows

// ==================== prep kernels ====================
__global__ void __launch_bounds__(256) convert_h_kernel(const float* __restrict__ in,
                                                        __half* __restrict__ out) {
    const size_t i = (size_t)blockIdx.x * 256 + threadIdx.x;
    float4 v = ((const float4*)in)[i];
    __half2* op = (__half2*)out;
    op[2 * i]     = __floats2half2_rn(v.x, v.y);
    op[2 * i + 1] = __floats2half2_rn(v.z, v.w);
}

// W: [K,N] fp32 -> [N,K] fp16, half2 stores. block (32,8), tile 64k x 32n.
__global__ void __launch_bounds__(256) splitT_kernel(const float* __restrict__ in,
                                                     __half* __restrict__ outT, int K, int N) {
    __shared__ float t[64][33];
    const int n0 = blockIdx.x * 32, k0 = blockIdx.y * 64;
    const int tx = threadIdx.x, ty = threadIdx.y;
    #pragma unroll
    for (int i = ty; i < 64; i += 8)
        t[i][tx] = in[(size_t)(k0 + i) * N + n0 + tx];
    __syncthreads();
    #pragma unroll
    for (int i = ty; i < 32; i += 8) {
        const __half2 hv = __floats2half2_rn(t[tx * 2][i], t[tx * 2 + 1][i]);
        *(__half2*)(outT + (size_t)(n0 + i) * K + k0 + tx * 2) = hv;
    }
}

// ==================== HMMA GEMM (CTA 128x128, warp 64x32, 2 CTAs/SM) ====================
#define STG_BYTES 32768          // 16KB A + 16KB B
#define GEMM_SMEM (3 * STG_BYTES)

__device__ __forceinline__ void gemm_load_stage(
    const __half* __restrict__ A, const __half* __restrict__ Bt,
    int bm, int bn, int K, int kk, uint32_t stg, int tid)
{
    #pragma unroll
    for (int i = 0; i < 4; i++) {
        const int ch = tid + i * 256;
        const int r = ch >> 3, cc = ch & 7;
        cp16(stg + SMEM_SWZ((uint32_t)(r * 128 + cc * 16)),
             A + (size_t)(bm + r) * K + kk + cc * 8);
    }
    #pragma unroll
    for (int i = 0; i < 4; i++) {
        const int ch = tid + i * 256;
        const int r = ch >> 3, cc = ch & 7;
        cp16(stg + 16384 + SMEM_SWZ((uint32_t)(r * 128 + cc * 16)),
             Bt + (size_t)(bn + r) * K + kk + cc * 8);
    }
}

__device__ __forceinline__ void store_qkv_elem(int row, int col, float a, float b,
                                               float* __restrict__ outK, float* __restrict__ outV) {
    const int bb = row >> 10, s = row & 1023;
    const int seg = col >> 12, w = col & 4095;
    const int h = w >> 7, dd = w & 127;
    const int bh = bb * 32 + h;
    const __half ha = __float2half_rn(a), hb = __float2half_rn(b);
    const __half2 hh = __halves2half2(ha, hb);
    const size_t i16 = ((size_t)bh * 1024 + s) * 128 + dd;
    if (seg == 0) {
        const __half la = __float2half_rn(a - __half2float(ha));
        const __half lb = __float2half_rn(b - __half2float(hb));
        *(__half2*)(g_qh + i16) = hh;
        *(__half2*)(g_ql + i16) = __halves2half2(la, lb);
    } else if (seg == 1) {
        const __half la = __float2half_rn(a - __half2float(ha));
        const __half lb = __float2half_rn(b - __half2float(hb));
        *(float2*)(outK + ((size_t)bh * 2048 + s) * 128 + dd) = float2{a, b};
        *(__half2*)(g_kh + i16) = hh;
        *(__half2*)(g_kl + i16) = __halves2half2(la, lb);
    } else {
        *(float2*)(outV + ((size_t)bh * 2048 + s) * 128 + dd) = float2{a, b};
        *(__half2*)(g_vh + i16) = hh;
    }
}

template <int MODE>
__global__ void __launch_bounds__(256, 2) gemm_hmma(
    const __half* __restrict__ A, const __half* __restrict__ Bt,
    const float* __restrict__ bias, int N, int K,
    float* __restrict__ out0, float* __restrict__ outK, float* __restrict__ outV)
{
    extern __shared__ char smem[];
    const uint32_t sb = smem_u32(smem);
    const int tid = threadIdx.x;
    const int bm = blockIdx.x * 128;
    const int bn = blockIdx.y * 128;
    const int wid = tid >> 5, lane = tid & 31;
    const int wm = (wid & 1) * 64;
    const int wn = (wid >> 1) * 32;

    const int arow = wm + (lane & 15);
    const int achb = lane >> 4;
    const int brow = wn + (lane & 7) + ((lane & 16) >> 1);
    const int bchb = (lane >> 3) & 1;

    float acc[4][4][4];
    #pragma unroll
    for (int i = 0; i < 4; i++)
        #pragma unroll
        for (int j = 0; j < 4; j++)
            #pragma unroll
            for (int e = 0; e < 4; e++) acc[i][j][e] = 0.f;

    const int T = K >> 6;

    #pragma unroll
    for (int s = 0; s < 2; s++) {
        gemm_load_stage(A, Bt, bm, bn, K, s * 64, sb + s * STG_BYTES, tid);
        cp_commit();
    }

    for (int kt = 0; kt < T; kt++) {
        if (kt < T - 2) cp_wait<1>(); else cp_wait<0>();
        __syncthreads();

        if (kt + 2 < T) {
            gemm_load_stage(A, Bt, bm, bn, K, (kt + 2) * 64,
                            sb + ((kt + 2) % 3) * STG_BYTES, tid);
            cp_commit();
        }

        const uint32_t stg = sb + (kt % 3) * STG_BYTES;
        const uint32_t Ab = stg, Bb = stg + 16384;

        #pragma unroll
        for (int ks = 0; ks < 4; ks++) {
            uint32_t bfr[4][2];
            #pragma unroll
            for (int j2 = 0; j2 < 2; j2++) {
                const int rr = brow + j2 * 16;
                const int ch = (ks * 2 + bchb) ^ (rr & 7);
                uint32_t r0, r1, r2, r3;
                LDSM_X4(r0, r1, r2, r3, Bb + (uint32_t)(rr * 128 + ch * 16));
                bfr[j2 * 2 + 0][0] = r0; bfr[j2 * 2 + 0][1] = r1;
                bfr[j2 * 2 + 1][0] = r2; bfr[j2 * 2 + 1][1] = r3;
            }
            #pragma unroll
            for (int i = 0; i < 4; i++) {
                const int rr = arow + i * 16;
                const int ch = (ks * 2 + achb) ^ (rr & 7);
                uint32_t a0, a1, a2, a3;
                LDSM_X4(a0, a1, a2, a3, Ab + (uint32_t)(rr * 128 + ch * 16));
                #pragma unroll
                for (int j = 0; j < 4; j++)
                    MMA16816(acc[i][j], a0, a1, a2, a3, bfr[j][0], bfr[j][1]);
            }
        }
    }

    // epilogue
    const int lr = lane >> 2, lc2 = (lane & 3) * 2;
    #pragma unroll
    for (int i = 0; i < 4; i++) {
        #pragma unroll
        for (int j = 0; j < 4; j++) {
            const int c = bn + wn + j * 8 + lc2;
            const float bx = __ldg(bias + c);
            const float by = __ldg(bias + c + 1);
            const int r0 = bm + wm + i * 16 + lr;
            const float v0 = acc[i][j][0] + bx, v1 = acc[i][j][1] + by;
            const float v2 = acc[i][j][2] + bx, v3 = acc[i][j][3] + by;
            if (MODE == 0) {
                *(float2*)(out0 + (size_t)r0 * N + c) = float2{v0, v1};
                *(float2*)(out0 + (size_t)(r0 + 8) * N + c) = float2{v2, v3};
            } else {
                store_qkv_elem(r0, c, v0, v1, outK, outV);
                store_qkv_elem(r0 + 8, c, v2, v3, outK, outV);
            }
        }
    }
}

// ==================== HMMA flash attention ====================
// CTA: 128 q-rows of one (b,h); 8 warps (m16 each); kv-tile 64.
// QK = qh*kh + ql*kh + qh*kl ; PV = ph*vh (denominator from rounded ph).
#define ATT_QH 0
#define ATT_QL 32768
#define ATT_STG0 65536
#define ATT_STG_SZ 49152   // Kh 16K | Kl 16K | Vh 16K
#define ATT_SMEM (ATT_STG0 + 2 * ATT_STG_SZ)

__device__ __forceinline__ void attn_load_tile(uint32_t dst, const __half* __restrict__ src,
                                               int tid) {
    // 64 rows x 128 halves (256B rows, swizzled)
    #pragma unroll
    for (int i = 0; i < 4; i++) {
        const int ch = tid + i * 256;
        const int r = ch >> 4, c = ch & 15;
        cp16(dst + SMEM_SWZ256((uint32_t)(r * 256 + c * 16)), src + (size_t)r * 128 + c * 8);
    }
}

__global__ void __launch_bounds__(256, 1) attn_hmma()
{
    extern __shared__ char smem[];
    const uint32_t sb = smem_u32(smem);
    const int qt = (int)gridDim.x - 1 - (int)blockIdx.x;   // longest-first schedule
    const int bh = blockIdx.y;
    const int b = bh >> 5, h = bh & 31;
    const int tid = threadIdx.x;
    const int wid = tid >> 5, lane = tid & 31;

    const size_t qoff = ((size_t)bh * 1024 + qt * 128) * 128;
    // Q tiles: 128 rows x 128 halves
    #pragma unroll
    for (int i = 0; i < 8; i++) {
        const int ch = tid + i * 256;
        const int r = ch >> 4, c = ch & 15;
        const uint32_t sw = SMEM_SWZ256((uint32_t)(r * 256 + c * 16));
        cp16(sb + ATT_QH + sw, g_qh + qoff + (size_t)r * 128 + c * 8);
        cp16(sb + ATT_QL + sw, g_ql + qoff + (size_t)r * 128 + c * 8);
    }
    cp_commit();

    const int nkt = 2 * qt + 2;
    const size_t kvbase = (size_t)bh * 1024 * 128;

    // preload stage 0
    {
        const uint32_t stg = sb + ATT_STG0;
        attn_load_tile(stg,         g_kh + kvbase, tid);
        attn_load_tile(stg + 16384, g_kl + kvbase, tid);
        attn_load_tile(stg + 32768, g_vh + kvbase, tid);
        cp_commit();
    }

    float o[16][4];
    #pragma unroll
    for (int nt = 0; nt < 16; nt++)
        #pragma unroll
        for (int e = 0; e < 4; e++) o[nt][e] = 0.f;
    float m1 = -INFINITY, m2 = -INFINITY, l1 = 0.f, l2 = 0.f;
    const float scale = 0.08838834764831845f;

    const int row1 = qt * 128 + wid * 16 + (lane >> 2);
    const int row2 = row1 + 8;
    const int wrow_min = qt * 128 + wid * 16;

    // frag addressing
    const int qar = wid * 16 + (lane & 15);
    const int qchb = lane >> 4;
    const int kbr = (lane & 7) + ((lane & 16) >> 1);
    const int kchb = (lane >> 3) & 1;
    const int vkv = lane & 15;
    const int vdc = lane >> 4;

    for (int kt = 0; kt < nkt; kt++) {
        const bool pf = (kt + 1 < nkt);
        if (pf) {
            const uint32_t stg = sb + ATT_STG0 + ((kt + 1) & 1) * ATT_STG_SZ;
            const size_t off = kvbase + (size_t)(kt + 1) * 64 * 128;
            attn_load_tile(stg,         g_kh + off, tid);
            attn_load_tile(stg + 16384, g_kl + off, tid);
            attn_load_tile(stg + 32768, g_vh + off, tid);
            cp_commit();
        }
        if (pf) cp_wait<1>(); else cp_wait<0>();
        __syncthreads();

        const bool active = (kt * 64) <= (wrow_min + 15);
        if (active) {
            const uint32_t stg = sb + ATT_STG0 + (kt & 1) * ATT_STG_SZ;
            const uint32_t Kh = stg, Kl = stg + 16384, Vh = stg + 32768;

            float s[8][4];
            #pragma unroll
            for (int nt = 0; nt < 8; nt++)
                #pragma unroll
                for (int e = 0; e < 4; e++) s[nt][e] = 0.f;

            // QK pass 1+2: (qh+ql) * kh
            #pragma unroll
            for (int ks = 0; ks < 8; ks++) {
                uint32_t bfr[8][2];
                #pragma unroll
                for (int j2 = 0; j2 < 4; j2++) {
                    const int rr = kbr + j2 * 16;
                    const int ch = (ks * 2 + kchb) ^ (lane & 7);
                    uint32_t r0, r1, r2, r3;
                    LDSM_X4(r0, r1, r2, r3, Kh + (uint32_t)(rr * 256 + ch * 16));
                    bfr[j2 * 2][0] = r0; bfr[j2 * 2][1] = r1;
                    bfr[j2 * 2 + 1][0] = r2; bfr[j2 * 2 + 1][1] = r3;
                }
                const int ch = (ks * 2 + qchb) ^ (qar & 7);
                uint32_t a0, a1, a2, a3;
                LDSM_X4(a0, a1, a2, a3, sb + ATT_QH + (uint32_t)(qar * 256 + ch * 16));
                #pragma unroll
                for (int j = 0; j < 8; j++) MMA16816(s[j], a0, a1, a2, a3, bfr[j][0], bfr[j][1]);
                LDSM_X4(a0, a1, a2, a3, sb + ATT_QL + (uint32_t)(qar * 256 + ch * 16));
                #pragma unroll
                for (int j = 0; j < 8; j++) MMA16816(s[j], a0, a1, a2, a3, bfr[j][0], bfr[j][1]);
            }
            // QK pass 3: qh * kl
            #pragma unroll
            for (int ks = 0; ks < 8; ks++) {
                uint32_t bfr[8][2];
                #pragma unroll
                for (int j2 = 0; j2 < 4; j2++) {
                    const int rr = kbr + j2 * 16;
                    const int ch = (ks * 2 + kchb) ^ (lane & 7);
                    uint32_t r0, r1, r2, r3;
                    LDSM_X4(r0, r1, r2, r3, Kl + (uint32_t)(rr * 256 + ch * 16));
                    bfr[j2 * 2][0] = r0; bfr[j2 * 2][1] = r1;
                    bfr[j2 * 2 + 1][0] = r2; bfr[j2 * 2 + 1][1] = r3;
                }
                const int ch = (ks * 2 + qchb) ^ (qar & 7);
                uint32_t a0, a1, a2, a3;
                LDSM_X4(a0, a1, a2, a3, sb + ATT_QH + (uint32_t)(qar * 256 + ch * 16));
                #pragma unroll
                for (int j = 0; j < 8; j++) MMA16816(s[j], a0, a1, a2, a3, bfr[j][0], bfr[j][1]);
            }

            // scale + mask + online softmax
            const bool need_mask = (kt * 64 + 63) > wrow_min;
            float mx1 = -INFINITY, mx2 = -INFINITY;
            #pragma unroll
            for (int nt = 0; nt < 8; nt++) {
                const int cg = kt * 64 + nt * 8 + (lane & 3) * 2;
                #pragma unroll
                for (int e = 0; e < 2; e++) {
                    float v = s[nt][e] * scale;
                    if (need_mask && (cg + e > row1)) v = -INFINITY;
                    s[nt][e] = v; mx1 = fmaxf(mx1, v);
                }
                #pragma unroll
                for (int e = 2; e < 4; e++) {
                    float v = s[nt][e] * scale;
                    if (need_mask && (cg + e - 2 > row2)) v = -INFINITY;
                    s[nt][e] = v; mx2 = fmaxf(mx2, v);
                }
            }
            mx1 = fmaxf(mx1, __shfl_xor_sync(0xffffffffu, mx1, 1));
            mx1 = fmaxf(mx1, __shfl_xor_sync(0xffffffffu, mx1, 2));
            mx2 = fmaxf(mx2, __shfl_xor_sync(0xffffffffu, mx2, 1));
            mx2 = fmaxf(mx2, __shfl_xor_sync(0xffffffffu, mx2, 2));
            const float mn1 = fmaxf(m1, mx1), mn2 = fmaxf(m2, mx2);
            const float c1 = __expf(m1 - mn1), c2 = __expf(m2 - mn2);
            m1 = mn1; m2 = mn2;

            uint32_t ph2[8][2];
            float ts1 = 0.f, ts2 = 0.f;
            #pragma unroll
            for (int nt = 0; nt < 8; nt++) {
                float p0 = __expf(s[nt][0] - mn1), p1 = __expf(s[nt][1] - mn1);
                float p2 = __expf(s[nt][2] - mn2), p3 = __expf(s[nt][3] - mn2);
                __half h0 = __float2half_rn(p0), h1 = __float2half_rn(p1);
                __half h2 = __float2half_rn(p2), h3 = __float2half_rn(p3);
                // denominator from the SAME rounded values the MMA uses
                ts1 += __half2float(h0) + __half2float(h1);
                ts2 += __half2float(h2) + __half2float(h3);
                ph2[nt][0] = h2_as_u32(__halves2half2(h0, h1));
                ph2[nt][1] = h2_as_u32(__halves2half2(h2, h3));
            }
            l1 = l1 * c1 + ts1; l2 = l2 * c2 + ts2;
            #pragma unroll
            for (int nt = 0; nt < 16; nt++) {
                o[nt][0] *= c1; o[nt][1] *= c1; o[nt][2] *= c2; o[nt][3] *= c2;
            }

            // PV: ph * vh
            #pragma unroll
            for (int ks = 0; ks < 4; ks++) {
                const uint32_t ah0 = ph2[2 * ks][0], ah1 = ph2[2 * ks][1];
                const uint32_t ah2 = ph2[2 * ks + 1][0], ah3 = ph2[2 * ks + 1][1];
                #pragma unroll
                for (int d2 = 0; d2 < 8; d2++) {
                    const int kvr = ks * 16 + vkv;
                    const int ch = (d2 * 2 + vdc) ^ (vkv & 7);
                    const uint32_t va = (uint32_t)(kvr * 256 + ch * 16);
                    uint32_t v0, v1, v2, v3;
                    LDSM_X4_T(v0, v1, v2, v3, Vh + va);
                    MMA16816(o[2 * d2],     ah0, ah1, ah2, ah3, v0, v1);
                    MMA16816(o[2 * d2 + 1], ah0, ah1, ah2, ah3, v2, v3);
                }
            }
        }
        __syncthreads();
    }

    l1 += __shfl_xor_sync(0xffffffffu, l1, 1);
    l1 += __shfl_xor_sync(0xffffffffu, l1, 2);
    l2 += __shfl_xor_sync(0xffffffffu, l2, 1);
    l2 += __shfl_xor_sync(0xffffffffu, l2, 2);
    const float i1 = 1.f / l1, i2 = 1.f / l2;

    __half* outp = g_aout_h;
    #pragma unroll
    for (int nt = 0; nt < 16; nt++) {
        const int col = h * 128 + nt * 8 + (lane & 3) * 2;
        *(__half2*)(outp + (size_t)(b * 1024 + row1) * 4096 + col) =
            __floats2half2_rn(o[nt][0] * i1, o[nt][1] * i1);
        *(__half2*)(outp + (size_t)(b * 1024 + row2) * 4096 + col) =
            __floats2half2_rn(o[nt][2] * i2, o[nt][3] * i2);
    }
}

// ==================== launch ====================
extern "C" void kernel_launch(void* const* d_in, const int* in_sizes, int n_in,
                              void* d_out, int out_size)
{
    const float* x       = (const float*)d_in[0];
    const float* W_qkv   = (const float*)d_in[2];
    const float* b_qkv   = (const float*)d_in[3];
    const float* W_out   = (const float*)d_in[4];
    const float* b_out   = (const float*)d_in[5];
    const float* cache_k = (const float*)d_in[6];
    const float* cache_v = (const float*)d_in[7];

    float* out  = (float*)d_out;
    float* y    = out;
    float* outK = out + 8388608;
    float* outV = out + 25165824;

    __half *ah, *aout, *bq, *wo;
    cudaGetSymbolAddress((void**)&ah, g_ah);
    cudaGetSymbolAddress((void**)&aout, g_aout_h);
    cudaGetSymbolAddress((void**)&bq, g_bqkv);
    cudaGetSymbolAddress((void**)&wo, g_wout);

    // tail-only cache preservation: slots [1024,2048) per (b,h); slots < 1024
    // are fully overwritten by the QKV epilogue.
    const size_t pitch = (size_t)2048 * 128 * sizeof(float);
    const size_t width = (size_t)1024 * 128 * sizeof(float);
    cudaMemcpy2DAsync(outK + (size_t)1024 * 128, pitch,
                      cache_k + (size_t)1024 * 128, pitch, width, 64,
                      cudaMemcpyDeviceToDevice, 0);
    cudaMemcpy2DAsync(outV + (size_t)1024 * 128, pitch,
                      cache_v + (size_t)1024 * 128, pitch, width, 64,
                      cudaMemcpyDeviceToDevice, 0);

    cudaFuncSetAttribute(gemm_hmma<0>, cudaFuncAttributeMaxDynamicSharedMemorySize, GEMM_SMEM);
    cudaFuncSetAttribute(gemm_hmma<1>, cudaFuncAttributeMaxDynamicSharedMemorySize, GEMM_SMEM);
    cudaFuncSetAttribute(attn_hmma, cudaFuncAttributeMaxDynamicSharedMemorySize, ATT_SMEM);

    convert_h_kernel<<<8192, 256>>>(x, ah);
    splitT_kernel<<<dim3(384, 64), dim3(32, 8)>>>(W_qkv, bq, 4096, 12288);
    splitT_kernel<<<dim3(128, 64), dim3(32, 8)>>>(W_out, wo, 4096, 4096);

    gemm_hmma<1><<<dim3(16, 96), 256, GEMM_SMEM>>>(ah, bq, b_qkv, 12288, 4096,
                                                   nullptr, outK, outV);

    attn_hmma<<<dim3(8, 64), 256, ATT_SMEM>>>();

    gemm_hmma<0><<<dim3(16, 32), 256, GEMM_SMEM>>>(aout, wo, b_out, 4096, 4096,
                                                   y, nullptr, nullptr);
}

// round 8
// speedup vs baseline: 6.3307x; 1.0631x over previous
#include <cuda_runtime.h>
#include <cuda_fp16.h>
#include <math.h>
#include <cstdint>

typedef unsigned long long u64;

// ==================== scratch ====================
__device__ __align__(128) __half g_ah[2048 * 4096];        // fp16(x) / A for QKV
__device__ __align__(128) __half g_aout_h[2048 * 4096];    // fp16 attn out / A for out-proj
__device__ __align__(128) __half g_qh[64 * 1024 * 128];
__device__ __align__(128) __half g_ql[64 * 1024 * 128];
__device__ __align__(128) __half g_kh[64 * 1024 * 128];
__device__ __align__(128) __half g_kl[64 * 1024 * 128];
__device__ __align__(128) __half g_vh[64 * 1024 * 128];
__device__ __align__(128) __half g_bqkv[12288 * 4096];     // [N,K] fp16
__device__ __align__(128) __half g_wout[4096 * 4096];      // [N,K] fp16

// ==================== PTX helpers ====================
__device__ __forceinline__ uint32_t smem_u32(const void* p) {
    uint32_t a;
    asm("{ .reg .u64 t; cvta.to.shared.u64 t, %1; cvt.u32.u64 %0, t; }" : "=r"(a) : "l"(p));
    return a;
}
__device__ __forceinline__ uint32_t h2_as_u32(__half2 h) {
    union { __half2 h2; uint32_t u; } cvt;
    cvt.h2 = h;
    return cvt.u;
}
__device__ __forceinline__ void cp16(uint32_t dst, const void* src) {
    asm volatile("cp.async.cg.shared.global [%0], [%1], 16;" :: "r"(dst), "l"(src));
}
__device__ __forceinline__ void cp_commit() { asm volatile("cp.async.commit_group;" ::: "memory"); }
template <int N> __device__ __forceinline__ void cp_wait() { asm volatile("cp.async.wait_group %0;" :: "n"(N) : "memory"); }

#define LDSM_X4(r0, r1, r2, r3, addr) \
    asm volatile("ldmatrix.sync.aligned.m8n8.x4.shared.b16 {%0,%1,%2,%3}, [%4];" \
        : "=r"(r0), "=r"(r1), "=r"(r2), "=r"(r3) : "r"(addr))
#define LDSM_X4_T(r0, r1, r2, r3, addr) \
    asm volatile("ldmatrix.sync.aligned.m8n8.x4.trans.shared.b16 {%0,%1,%2,%3}, [%4];" \
        : "=r"(r0), "=r"(r1), "=r"(r2), "=r"(r3) : "r"(addr))

#define MMA16816(d, a0, a1, a2, a3, b0, b1) \
    asm volatile("mma.sync.aligned.m16n8k16.row.col.f32.f16.f16.f32 " \
        "{%0,%1,%2,%3},{%4,%5,%6,%7},{%8,%9},{%0,%1,%2,%3};" \
        : "+f"((d)[0]), "+f"((d)[1]), "+f"((d)[2]), "+f"((d)[3]) \
        : "r"(a0), "r"(a1), "r"(a2), "r"(a3), "r"(b0), "r"(b1))

#define SMEM_SWZ(off)    ((off) ^ (((off) >> 3) & 0x70))   // 128B rows
#define SMEM_SWZ256(off) ((off) ^ (((off) >> 4) & 0x70))   // 256B rows

// ==================== prep kernels ====================
__global__ void __launch_bounds__(256) convert_h_kernel(const float* __restrict__ in,
                                                        __half* __restrict__ out) {
    const size_t i = (size_t)blockIdx.x * 256 + threadIdx.x;
    float4 v = ((const float4*)in)[i];
    __half2* op = (__half2*)out;
    op[2 * i]     = __floats2half2_rn(v.x, v.y);
    op[2 * i + 1] = __floats2half2_rn(v.z, v.w);
}

// W: [K,N] fp32 -> [N,K] fp16, half2 stores. block (32,8), tile 64k x 32n.
__global__ void __launch_bounds__(256) splitT_kernel(const float* __restrict__ in,
                                                     __half* __restrict__ outT, int K, int N) {
    __shared__ float t[64][33];
    const int n0 = blockIdx.x * 32, k0 = blockIdx.y * 64;
    const int tx = threadIdx.x, ty = threadIdx.y;
    #pragma unroll
    for (int i = ty; i < 64; i += 8)
        t[i][tx] = in[(size_t)(k0 + i) * N + n0 + tx];
    __syncthreads();
    #pragma unroll
    for (int i = ty; i < 32; i += 8) {
        const __half2 hv = __floats2half2_rn(t[tx * 2][i], t[tx * 2 + 1][i]);
        *(__half2*)(outT + (size_t)(n0 + i) * K + k0 + tx * 2) = hv;
    }
}

// ==================== HMMA GEMM (CTA 128x128, warp 64x32, 2 CTAs/SM) ====================
#define STG_BYTES 32768          // 16KB A + 16KB B
#define GEMM_SMEM (3 * STG_BYTES)

__device__ __forceinline__ void gemm_load_stage(
    const __half* __restrict__ A, const __half* __restrict__ Bt,
    int bm, int bn, int K, int kk, uint32_t stg, int tid)
{
    #pragma unroll
    for (int i = 0; i < 4; i++) {
        const int ch = tid + i * 256;
        const int r = ch >> 3, cc = ch & 7;
        cp16(stg + SMEM_SWZ((uint32_t)(r * 128 + cc * 16)),
             A + (size_t)(bm + r) * K + kk + cc * 8);
    }
    #pragma unroll
    for (int i = 0; i < 4; i++) {
        const int ch = tid + i * 256;
        const int r = ch >> 3, cc = ch & 7;
        cp16(stg + 16384 + SMEM_SWZ((uint32_t)(r * 128 + cc * 16)),
             Bt + (size_t)(bn + r) * K + kk + cc * 8);
    }
}

__device__ __forceinline__ void store_qkv_elem(int row, int col, float a, float b,
                                               float* __restrict__ outK, float* __restrict__ outV) {
    const int bb = row >> 10, s = row & 1023;
    const int seg = col >> 12, w = col & 4095;
    const int h = w >> 7, dd = w & 127;
    const int bh = bb * 32 + h;
    const __half ha = __float2half_rn(a), hb = __float2half_rn(b);
    const __half2 hh = __halves2half2(ha, hb);
    const size_t i16 = ((size_t)bh * 1024 + s) * 128 + dd;
    if (seg == 0) {
        const __half la = __float2half_rn(a - __half2float(ha));
        const __half lb = __float2half_rn(b - __half2float(hb));
        *(__half2*)(g_qh + i16) = hh;
        *(__half2*)(g_ql + i16) = __halves2half2(la, lb);
    } else if (seg == 1) {
        const __half la = __float2half_rn(a - __half2float(ha));
        const __half lb = __float2half_rn(b - __half2float(hb));
        *(float2*)(outK + ((size_t)bh * 2048 + s) * 128 + dd) = float2{a, b};
        *(__half2*)(g_kh + i16) = hh;
        *(__half2*)(g_kl + i16) = __halves2half2(la, lb);
    } else {
        *(float2*)(outV + ((size_t)bh * 2048 + s) * 128 + dd) = float2{a, b};
        *(__half2*)(g_vh + i16) = hh;
    }
}

template <int MODE>
__global__ void __launch_bounds__(256, 2) gemm_hmma(
    const __half* __restrict__ A, const __half* __restrict__ Bt,
    const float* __restrict__ bias, int N, int K,
    float* __restrict__ out0, float* __restrict__ outK, float* __restrict__ outV)
{
    extern __shared__ char smem[];
    const uint32_t sb = smem_u32(smem);
    const int tid = threadIdx.x;
    const int bm = blockIdx.x * 128;
    const int bn = blockIdx.y * 128;
    const int wid = tid >> 5, lane = tid & 31;
    const int wm = (wid & 1) * 64;
    const int wn = (wid >> 1) * 32;

    const int arow = wm + (lane & 15);
    const int achb = lane >> 4;
    const int brow = wn + (lane & 7) + ((lane & 16) >> 1);
    const int bchb = (lane >> 3) & 1;

    float acc[4][4][4];
    #pragma unroll
    for (int i = 0; i < 4; i++)
        #pragma unroll
        for (int j = 0; j < 4; j++)
            #pragma unroll
            for (int e = 0; e < 4; e++) acc[i][j][e] = 0.f;

    const int T = K >> 6;

    #pragma unroll
    for (int s = 0; s < 2; s++) {
        gemm_load_stage(A, Bt, bm, bn, K, s * 64, sb + s * STG_BYTES, tid);
        cp_commit();
    }

    for (int kt = 0; kt < T; kt++) {
        if (kt < T - 2) cp_wait<1>(); else cp_wait<0>();
        __syncthreads();

        if (kt + 2 < T) {
            gemm_load_stage(A, Bt, bm, bn, K, (kt + 2) * 64,
                            sb + ((kt + 2) % 3) * STG_BYTES, tid);
            cp_commit();
        }

        const uint32_t stg = sb + (kt % 3) * STG_BYTES;
        const uint32_t Ab = stg, Bb = stg + 16384;

        #pragma unroll
        for (int ks = 0; ks < 4; ks++) {
            uint32_t bfr[4][2];
            #pragma unroll
            for (int j2 = 0; j2 < 2; j2++) {
                const int rr = brow + j2 * 16;
                const int ch = (ks * 2 + bchb) ^ (rr & 7);
                uint32_t r0, r1, r2, r3;
                LDSM_X4(r0, r1, r2, r3, Bb + (uint32_t)(rr * 128 + ch * 16));
                bfr[j2 * 2 + 0][0] = r0; bfr[j2 * 2 + 0][1] = r1;
                bfr[j2 * 2 + 1][0] = r2; bfr[j2 * 2 + 1][1] = r3;
            }
            #pragma unroll
            for (int i = 0; i < 4; i++) {
                const int rr = arow + i * 16;
                const int ch = (ks * 2 + achb) ^ (rr & 7);
                uint32_t a0, a1, a2, a3;
                LDSM_X4(a0, a1, a2, a3, Ab + (uint32_t)(rr * 128 + ch * 16));
                #pragma unroll
                for (int j = 0; j < 4; j++)
                    MMA16816(acc[i][j], a0, a1, a2, a3, bfr[j][0], bfr[j][1]);
            }
        }
    }

    // epilogue
    const int lr = lane >> 2, lc2 = (lane & 3) * 2;
    #pragma unroll
    for (int i = 0; i < 4; i++) {
        #pragma unroll
        for (int j = 0; j < 4; j++) {
            const int c = bn + wn + j * 8 + lc2;
            const float bx = __ldg(bias + c);
            const float by = __ldg(bias + c + 1);
            const int r0 = bm + wm + i * 16 + lr;
            const float v0 = acc[i][j][0] + bx, v1 = acc[i][j][1] + by;
            const float v2 = acc[i][j][2] + bx, v3 = acc[i][j][3] + by;
            if (MODE == 0) {
                *(float2*)(out0 + (size_t)r0 * N + c) = float2{v0, v1};
                *(float2*)(out0 + (size_t)(r0 + 8) * N + c) = float2{v2, v3};
            } else {
                store_qkv_elem(r0, c, v0, v1, outK, outV);
                store_qkv_elem(r0 + 8, c, v2, v3, outK, outV);
            }
        }
    }
}

// ==================== HMMA flash attention ====================
// CTA: 128 q-rows of one (b,h); 8 warps (m16 each); kv-tile 64.
// QK = qh*kh + ql*kh + qh*kl ; PV = ph*vh (denominator from rounded ph).
#define ATT_QH 0
#define ATT_QL 32768
#define ATT_STG0 65536
#define ATT_STG_SZ 49152   // Kh 16K | Kl 16K | Vh 16K
#define ATT_SMEM (ATT_STG0 + 2 * ATT_STG_SZ)

__device__ __forceinline__ void attn_load_tile(uint32_t dst, const __half* __restrict__ src,
                                               int tid) {
    // 64 rows x 128 halves (256B rows, swizzled)
    #pragma unroll
    for (int i = 0; i < 4; i++) {
        const int ch = tid + i * 256;
        const int r = ch >> 4, c = ch & 15;
        cp16(dst + SMEM_SWZ256((uint32_t)(r * 256 + c * 16)), src + (size_t)r * 128 + c * 8);
    }
}

__global__ void __launch_bounds__(256, 1) attn_hmma()
{
    extern __shared__ char smem[];
    const uint32_t sb = smem_u32(smem);
    const int qt = (int)gridDim.x - 1 - (int)blockIdx.x;   // longest-first schedule
    const int bh = blockIdx.y;
    const int b = bh >> 5, h = bh & 31;
    const int tid = threadIdx.x;
    const int wid = tid >> 5, lane = tid & 31;

    const size_t qoff = ((size_t)bh * 1024 + qt * 128) * 128;
    // Q tiles: 128 rows x 128 halves
    #pragma unroll
    for (int i = 0; i < 8; i++) {
        const int ch = tid + i * 256;
        const int r = ch >> 4, c = ch & 15;
        const uint32_t sw = SMEM_SWZ256((uint32_t)(r * 256 + c * 16));
        cp16(sb + ATT_QH + sw, g_qh + qoff + (size_t)r * 128 + c * 8);
        cp16(sb + ATT_QL + sw, g_ql + qoff + (size_t)r * 128 + c * 8);
    }
    cp_commit();

    const int nkt = 2 * qt + 2;
    const size_t kvbase = (size_t)bh * 1024 * 128;

    // preload stage 0
    {
        const uint32_t stg = sb + ATT_STG0;
        attn_load_tile(stg,         g_kh + kvbase, tid);
        attn_load_tile(stg + 16384, g_kl + kvbase, tid);
        attn_load_tile(stg + 32768, g_vh + kvbase, tid);
        cp_commit();
    }

    float o[16][4];
    #pragma unroll
    for (int nt = 0; nt < 16; nt++)
        #pragma unroll
        for (int e = 0; e < 4; e++) o[nt][e] = 0.f;
    float m1 = -INFINITY, m2 = -INFINITY, l1 = 0.f, l2 = 0.f;
    const float scale = 0.08838834764831845f;

    const int row1 = qt * 128 + wid * 16 + (lane >> 2);
    const int row2 = row1 + 8;
    const int wrow_min = qt * 128 + wid * 16;

    // frag addressing
    const int qar = wid * 16 + (lane & 15);
    const int qchb = lane >> 4;
    const int kbr = (lane & 7) + ((lane & 16) >> 1);
    const int kchb = (lane >> 3) & 1;
    const int vkv = lane & 15;
    const int vdc = lane >> 4;

    for (int kt = 0; kt < nkt; kt++) {
        const bool pf = (kt + 1 < nkt);
        if (pf) {
            const uint32_t stg = sb + ATT_STG0 + ((kt + 1) & 1) * ATT_STG_SZ;
            const size_t off = kvbase + (size_t)(kt + 1) * 64 * 128;
            attn_load_tile(stg,         g_kh + off, tid);
            attn_load_tile(stg + 16384, g_kl + off, tid);
            attn_load_tile(stg + 32768, g_vh + off, tid);
            cp_commit();
        }
        if (pf) cp_wait<1>(); else cp_wait<0>();
        __syncthreads();

        const bool active = (kt * 64) <= (wrow_min + 15);
        if (active) {
            const uint32_t stg = sb + ATT_STG0 + (kt & 1) * ATT_STG_SZ;
            const uint32_t Kh = stg, Kl = stg + 16384, Vh = stg + 32768;

            float s[8][4];
            #pragma unroll
            for (int nt = 0; nt < 8; nt++)
                #pragma unroll
                for (int e = 0; e < 4; e++) s[nt][e] = 0.f;

            // QK pass 1+2: (qh+ql) * kh
            #pragma unroll
            for (int ks = 0; ks < 8; ks++) {
                uint32_t bfr[8][2];
                #pragma unroll
                for (int j2 = 0; j2 < 4; j2++) {
                    const int rr = kbr + j2 * 16;
                    const int ch = (ks * 2 + kchb) ^ (lane & 7);
                    uint32_t r0, r1, r2, r3;
                    LDSM_X4(r0, r1, r2, r3, Kh + (uint32_t)(rr * 256 + ch * 16));
                    bfr[j2 * 2][0] = r0; bfr[j2 * 2][1] = r1;
                    bfr[j2 * 2 + 1][0] = r2; bfr[j2 * 2 + 1][1] = r3;
                }
                const int ch = (ks * 2 + qchb) ^ (qar & 7);
                uint32_t a0, a1, a2, a3;
                LDSM_X4(a0, a1, a2, a3, sb + ATT_QH + (uint32_t)(qar * 256 + ch * 16));
                #pragma unroll
                for (int j = 0; j < 8; j++) MMA16816(s[j], a0, a1, a2, a3, bfr[j][0], bfr[j][1]);
                LDSM_X4(a0, a1, a2, a3, sb + ATT_QL + (uint32_t)(qar * 256 + ch * 16));
                #pragma unroll
                for (int j = 0; j < 8; j++) MMA16816(s[j], a0, a1, a2, a3, bfr[j][0], bfr[j][1]);
            }
            // QK pass 3: qh * kl
            #pragma unroll
            for (int ks = 0; ks < 8; ks++) {
                uint32_t bfr[8][2];
                #pragma unroll
                for (int j2 = 0; j2 < 4; j2++) {
                    const int rr = kbr + j2 * 16;
                    const int ch = (ks * 2 + kchb) ^ (lane & 7);
                    uint32_t r0, r1, r2, r3;
                    LDSM_X4(r0, r1, r2, r3, Kl + (uint32_t)(rr * 256 + ch * 16));
                    bfr[j2 * 2][0] = r0; bfr[j2 * 2][1] = r1;
                    bfr[j2 * 2 + 1][0] = r2; bfr[j2 * 2 + 1][1] = r3;
                }
                const int ch = (ks * 2 + qchb) ^ (qar & 7);
                uint32_t a0, a1, a2, a3;
                LDSM_X4(a0, a1, a2, a3, sb + ATT_QH + (uint32_t)(qar * 256 + ch * 16));
                #pragma unroll
                for (int j = 0; j < 8; j++) MMA16816(s[j], a0, a1, a2, a3, bfr[j][0], bfr[j][1]);
            }

            // scale + mask + online softmax
            const bool need_mask = (kt * 64 + 63) > wrow_min;
            float mx1 = -INFINITY, mx2 = -INFINITY;
            #pragma unroll
            for (int nt = 0; nt < 8; nt++) {
                const int cg = kt * 64 + nt * 8 + (lane & 3) * 2;
                #pragma unroll
                for (int e = 0; e < 2; e++) {
                    float v = s[nt][e] * scale;
                    if (need_mask && (cg + e > row1)) v = -INFINITY;
                    s[nt][e] = v; mx1 = fmaxf(mx1, v);
                }
                #pragma unroll
                for (int e = 2; e < 4; e++) {
                    float v = s[nt][e] * scale;
                    if (need_mask && (cg + e - 2 > row2)) v = -INFINITY;
                    s[nt][e] = v; mx2 = fmaxf(mx2, v);
                }
            }
            mx1 = fmaxf(mx1, __shfl_xor_sync(0xffffffffu, mx1, 1));
            mx1 = fmaxf(mx1, __shfl_xor_sync(0xffffffffu, mx1, 2));
            mx2 = fmaxf(mx2, __shfl_xor_sync(0xffffffffu, mx2, 1));
            mx2 = fmaxf(mx2, __shfl_xor_sync(0xffffffffu, mx2, 2));
            const float mn1 = fmaxf(m1, mx1), mn2 = fmaxf(m2, mx2);
            const float c1 = __expf(m1 - mn1), c2 = __expf(m2 - mn2);
            m1 = mn1; m2 = mn2;

            uint32_t ph2[8][2];
            float ts1 = 0.f, ts2 = 0.f;
            #pragma unroll
            for (int nt = 0; nt < 8; nt++) {
                float p0 = __expf(s[nt][0] - mn1), p1 = __expf(s[nt][1] - mn1);
                float p2 = __expf(s[nt][2] - mn2), p3 = __expf(s[nt][3] - mn2);
                __half h0 = __float2half_rn(p0), h1 = __float2half_rn(p1);
                __half h2 = __float2half_rn(p2), h3 = __float2half_rn(p3);
                // denominator from the SAME rounded values the MMA uses
                ts1 += __half2float(h0) + __half2float(h1);
                ts2 += __half2float(h2) + __half2float(h3);
                ph2[nt][0] = h2_as_u32(__halves2half2(h0, h1));
                ph2[nt][1] = h2_as_u32(__halves2half2(h2, h3));
            }
            l1 = l1 * c1 + ts1; l2 = l2 * c2 + ts2;
            #pragma unroll
            for (int nt = 0; nt < 16; nt++) {
                o[nt][0] *= c1; o[nt][1] *= c1; o[nt][2] *= c2; o[nt][3] *= c2;
            }

            // PV: ph * vh
            #pragma unroll
            for (int ks = 0; ks < 4; ks++) {
                const uint32_t ah0 = ph2[2 * ks][0], ah1 = ph2[2 * ks][1];
                const uint32_t ah2 = ph2[2 * ks + 1][0], ah3 = ph2[2 * ks + 1][1];
                #pragma unroll
                for (int d2 = 0; d2 < 8; d2++) {
                    const int kvr = ks * 16 + vkv;
                    const int ch = (d2 * 2 + vdc) ^ (vkv & 7);
                    const uint32_t va = (uint32_t)(kvr * 256 + ch * 16);
                    uint32_t v0, v1, v2, v3;
                    LDSM_X4_T(v0, v1, v2, v3, Vh + va);
                    MMA16816(o[2 * d2],     ah0, ah1, ah2, ah3, v0, v1);
                    MMA16816(o[2 * d2 + 1], ah0, ah1, ah2, ah3, v2, v3);
                }
            }
        }
        __syncthreads();
    }

    l1 += __shfl_xor_sync(0xffffffffu, l1, 1);
    l1 += __shfl_xor_sync(0xffffffffu, l1, 2);
    l2 += __shfl_xor_sync(0xffffffffu, l2, 1);
    l2 += __shfl_xor_sync(0xffffffffu, l2, 2);
    const float i1 = 1.f / l1, i2 = 1.f / l2;

    __half* outp = g_aout_h;
    #pragma unroll
    for (int nt = 0; nt < 16; nt++) {
        const int col = h * 128 + nt * 8 + (lane & 3) * 2;
        *(__half2*)(outp + (size_t)(b * 1024 + row1) * 4096 + col) =
            __floats2half2_rn(o[nt][0] * i1, o[nt][1] * i1);
        *(__half2*)(outp + (size_t)(b * 1024 + row2) * 4096 + col) =
            __floats2half2_rn(o[nt][2] * i2, o[nt][3] * i2);
    }
}

// ==================== launch ====================
extern "C" void kernel_launch(void* const* d_in, const int* in_sizes, int n_in,
                              void* d_out, int out_size)
{
    const float* x       = (const float*)d_in[0];
    const float* W_qkv   = (const float*)d_in[2];
    const float* b_qkv   = (const float*)d_in[3];
    const float* W_out   = (const float*)d_in[4];
    const float* b_out   = (const float*)d_in[5];
    const float* cache_k = (const float*)d_in[6];
    const float* cache_v = (const float*)d_in[7];

    float* out  = (float*)d_out;
    float* y    = out;
    float* outK = out + 8388608;
    float* outV = out + 25165824;

    __half *ah, *aout, *bq, *wo;
    cudaGetSymbolAddress((void**)&ah, g_ah);
    cudaGetSymbolAddress((void**)&aout, g_aout_h);
    cudaGetSymbolAddress((void**)&bq, g_bqkv);
    cudaGetSymbolAddress((void**)&wo, g_wout);

    // one-time side-stream + fork/join events (no device memory involved)
    static cudaStream_t s1 = nullptr;
    static cudaEvent_t evFork = nullptr, evConv = nullptr, evPrep = nullptr;
    if (s1 == nullptr) {
        cudaStreamCreateWithFlags(&s1, cudaStreamNonBlocking);
        cudaEventCreateWithFlags(&evFork, cudaEventDisableTiming);
        cudaEventCreateWithFlags(&evConv, cudaEventDisableTiming);
        cudaEventCreateWithFlags(&evPrep, cudaEventDisableTiming);
    }

    cudaFuncSetAttribute(gemm_hmma<0>, cudaFuncAttributeMaxDynamicSharedMemorySize, GEMM_SMEM);
    cudaFuncSetAttribute(gemm_hmma<1>, cudaFuncAttributeMaxDynamicSharedMemorySize, GEMM_SMEM);
    cudaFuncSetAttribute(attn_hmma, cudaFuncAttributeMaxDynamicSharedMemorySize, ATT_SMEM);

    // ---- fork side stream ----
    cudaEventRecord(evFork, 0);
    cudaStreamWaitEvent(s1, evFork, 0);

    // side stream: x->fp16, cache tail copies, W_out transpose
    convert_h_kernel<<<8192, 256, 0, s1>>>(x, ah);
    cudaEventRecord(evConv, s1);
    {
        const size_t pitch = (size_t)2048 * 128 * sizeof(float);
        const size_t width = (size_t)1024 * 128 * sizeof(float);
        cudaMemcpy2DAsync(outK + (size_t)1024 * 128, pitch,
                          cache_k + (size_t)1024 * 128, pitch, width, 64,
                          cudaMemcpyDeviceToDevice, s1);
        cudaMemcpy2DAsync(outV + (size_t)1024 * 128, pitch,
                          cache_v + (size_t)1024 * 128, pitch, width, 64,
                          cudaMemcpyDeviceToDevice, s1);
    }
    splitT_kernel<<<dim3(128, 64), dim3(32, 8), 0, s1>>>(W_out, wo, 4096, 4096);
    cudaEventRecord(evPrep, s1);

    // main stream: W_qkv transpose runs concurrently with side stream
    splitT_kernel<<<dim3(384, 64), dim3(32, 8)>>>(W_qkv, bq, 4096, 12288);

    // QKV GEMM needs g_ah (side stream)
    cudaStreamWaitEvent(0, evConv, 0);
    gemm_hmma<1><<<dim3(16, 96), 256, GEMM_SMEM>>>(ah, bq, b_qkv, 12288, 4096,
                                                   nullptr, outK, outV);

    attn_hmma<<<dim3(8, 64), 256, ATT_SMEM>>>();

    // out-proj needs g_wout (side stream) — join before launch
    cudaStreamWaitEvent(0, evPrep, 0);
    gemm_hmma<0><<<dim3(16, 32), 256, GEMM_SMEM>>>(aout, wo, b_out, 4096, 4096,
                                                   y, nullptr, nullptr);
}